// round 5
// baseline (speedup 1.0000x reference)
#include <cuda_runtime.h>
#include <cuda_bf16.h>
#include <cstdint>

// ---------------- problem constants ----------------
constexpr int N_TOK  = 2048 * 64;   // 131072 tokens
constexpr int EMB    = 384;
constexpr int NHEAD  = 8;
constexpr int HSZ    = 48;
constexpr int SEQ    = 64;
constexpr int FF     = 1536;
constexpr float ATT_SCALE = 2.449489742783178f;

// ---------------- scratch (static device memory) ----------------
__device__ __align__(128) __nv_bfloat16 g_ln1 [(size_t)N_TOK * 2 * EMB];   // [hi|lo]
__device__ __align__(128) float         g_qkv [(size_t)N_TOK * 3 * EMB];   // fp32 q|k|v
__device__ __align__(128) __nv_bfloat16 g_attn[(size_t)N_TOK * 2 * EMB];   // [hi|lo]
__device__ __align__(128) float         g_x2  [(size_t)N_TOK * EMB];       // fp32 residual
__device__ __align__(128) __nv_bfloat16 g_h2  [(size_t)N_TOK * 2 * EMB];   // [hi|lo]
__device__ __align__(128) __nv_bfloat16 g_hid [(size_t)N_TOK * 2 * FF];    // [hi|lo]
__device__ __align__(128) __nv_bfloat16 g_wqkv[(size_t)(3*EMB) * 2 * EMB]; // [N][2K] hi|lo
__device__ __align__(128) __nv_bfloat16 g_wp  [(size_t)EMB * 2 * EMB];
__device__ __align__(128) __nv_bfloat16 g_w1  [(size_t)FF  * 2 * EMB];
__device__ __align__(128) __nv_bfloat16 g_w2  [(size_t)EMB * 2 * FF];

// ---------------- PTX helpers ----------------
__device__ __forceinline__ uint32_t smem_u32(const void* p) {
    uint32_t a;
    asm("{ .reg .u64 t; cvta.to.shared.u64 t, %1; cvt.u32.u64 %0, t; }" : "=r"(a) : "l"(p));
    return a;
}
#define LDSM4(r, addr) \
    asm volatile("ldmatrix.sync.aligned.m8n8.x4.shared.b16 {%0,%1,%2,%3}, [%4];" \
        : "=r"((r)[0]), "=r"((r)[1]), "=r"((r)[2]), "=r"((r)[3]) : "r"(addr))

#define MMA16816(d, a, b0, b1) \
    asm volatile("mma.sync.aligned.m16n8k16.row.col.f32.bf16.bf16.f32 " \
        "{%0,%1,%2,%3}, {%4,%5,%6,%7}, {%8,%9}, {%0,%1,%2,%3};" \
        : "+f"((d)[0]), "+f"((d)[1]), "+f"((d)[2]), "+f"((d)[3]) \
        : "r"((a)[0]), "r"((a)[1]), "r"((a)[2]), "r"((a)[3]), "r"(b0), "r"(b1))

__device__ __forceinline__ __nv_bfloat16 bf_hi(float v) { return __float2bfloat16(v); }
__device__ __forceinline__ __nv_bfloat16 bf_lo(float v, __nv_bfloat16 hi) {
    return __float2bfloat16(v - __bfloat162float(hi));
}

// ---------------- weight prep ----------------
__global__ void prep_w_kernel(const float* __restrict__ W, __nv_bfloat16* __restrict__ out,
                              int K, int N) {
    int i = blockIdx.x * blockDim.x + threadIdx.x;
    if (i >= K * N) return;
    int k = i / N, n = i % N;
    float v = W[i];
    __nv_bfloat16 hi = bf_hi(v);
    out[(size_t)n * 2 * K + k]     = hi;
    out[(size_t)n * 2 * K + K + k] = bf_lo(v, hi);
}
__global__ void prep_wqkv_kernel(const float* __restrict__ Wq, const float* __restrict__ Wk,
                                 const float* __restrict__ Wv) {
    int i = blockIdx.x * blockDim.x + threadIdx.x;
    if (i >= NHEAD * EMB * HSZ) return;
    int h = i / (EMB * HSZ), r = i % (EMB * HSZ), c = r / HSZ, d = r % HSZ;
    int n = h * HSZ + d;
    float q = Wq[i], k = Wk[i], v = Wv[i];
    __nv_bfloat16 qh = bf_hi(q), kh = bf_hi(k), vh = bf_hi(v);
    size_t rq = (size_t)n * 2 * EMB, rk = (size_t)(EMB + n) * 2 * EMB, rv = (size_t)(2 * EMB + n) * 2 * EMB;
    g_wqkv[rq + c] = qh;  g_wqkv[rq + EMB + c] = bf_lo(q, qh);
    g_wqkv[rk + c] = kh;  g_wqkv[rk + EMB + c] = bf_lo(k, kh);
    g_wqkv[rv + c] = vh;  g_wqkv[rv + EMB + c] = bf_lo(v, vh);
}

// ---------------- layernorm -> split bf16 [hi|lo] ----------------
__global__ void ln_split_kernel(const float* __restrict__ in, const float* __restrict__ g,
                                const float* __restrict__ b, __nv_bfloat16* __restrict__ out) {
    int row = blockIdx.x;
    int t = threadIdx.x;  // 0..95
    float4 v = ((const float4*)(in + (size_t)row * EMB))[t];
    float s  = v.x + v.y + v.z + v.w;
    float ss = v.x * v.x + v.y * v.y + v.z * v.z + v.w * v.w;
    #pragma unroll
    for (int off = 16; off > 0; off >>= 1) {
        s  += __shfl_down_sync(0xffffffffu, s, off);
        ss += __shfl_down_sync(0xffffffffu, ss, off);
    }
    __shared__ float red0[3], red1[3];
    int w = t >> 5, l = t & 31;
    if (l == 0) { red0[w] = s; red1[w] = ss; }
    __syncthreads();
    float S = red0[0] + red0[1] + red0[2];
    float SS = red1[0] + red1[1] + red1[2];
    float mu = S * (1.0f / EMB);
    float var = SS * (1.0f / EMB) - mu * mu;
    float rs = rsqrtf(var + 1e-5f);
    float4 gv = ((const float4*)g)[t];
    float4 bv = ((const float4*)b)[t];
    float o[4] = {(v.x - mu) * rs * gv.x + bv.x, (v.y - mu) * rs * gv.y + bv.y,
                  (v.z - mu) * rs * gv.z + bv.z, (v.w - mu) * rs * gv.w + bv.w};
    __nv_bfloat16* orow = out + (size_t)row * 2 * EMB;
    __nv_bfloat162 hi2[2], lo2[2];
    #pragma unroll
    for (int j = 0; j < 2; j++) {
        __nv_bfloat16 h0 = bf_hi(o[2 * j]), h1 = bf_hi(o[2 * j + 1]);
        hi2[j] = __nv_bfloat162(h0, h1);
        lo2[j] = __nv_bfloat162(bf_lo(o[2 * j], h0), bf_lo(o[2 * j + 1], h1));
    }
    *(uint2*)(orow + 4 * t)       = *(uint2*)hi2;
    *(uint2*)(orow + EMB + 4 * t) = *(uint2*)lo2;
}

// ---------------- B-resident warp-MMA split-bf16 GEMM ----------------
// C[M,128] = A[M,K=384] @ B[128,384]^T. B resident in smem (hi+lo, 192KB).
// A single-buffered (16KB), staged via reg-prefetched LDG.128 + STS.128.
// BM=128, BK=32, 256 threads, warps 4(M)x2(N), warp tile 32x64, 3 MMA passes.
// Each CTA handles 16 M-blocks (gridDim.y = 64).
// 16B-chunk XOR swizzle: chunk' = chunk ^ (row & 7).
constexpr int BSMEM  = 128 * 1536;            // 196608 B resident
constexpr int ASMEM  = 128 * 128;             // 16384 A stage
constexpr int GSMEM  = BSMEM + ASMEM;         // 212992
constexpr int KSTEPS = 12;                    // K = 384, BK = 32
constexpr int MCHUNK = 16;

template<int MODE>  // 0: out=acc  1: out=acc+bias+res  2: out=split-bf16(relu(acc+bias))  3: out+=acc
__global__ void __launch_bounds__(256, 1)
gemm_tc(const __nv_bfloat16* __restrict__ A, int Astride, int Ahi_off, int Alo_off,
        const __nv_bfloat16* __restrict__ B, int Bstride, int Bhi_off, int Blo_off,
        const float* __restrict__ bias, const float* __restrict__ res,
        void* __restrict__ out, int Ntot) {
    extern __shared__ char smem[];
    const uint32_t sB = smem_u32(smem);
    const uint32_t sA = sB + BSMEM;
    const int tid = threadIdx.x, lane = tid & 31, wid = tid >> 5;
    const int wm = wid >> 1, wn = wid & 1;
    const int n0 = blockIdx.x * 128;

    // ---- one-time B load: 128 rows x 96 chunks of 16B ----
    {
        const __nv_bfloat16* Bn = B + (size_t)n0 * Bstride;
        #pragma unroll 4
        for (int i = 0; i < 48; i++) {
            int cg = i * 256 + tid;
            int row = cg / 96, c = cg - row * 96;
            int eoff = row * Bstride + (c < 48 ? Bhi_off + c * 8 : Blo_off + (c - 48) * 8);
            uint4 v = *(const uint4*)(Bn + eoff);
            *(uint4*)(smem + row * 1536 + ((c ^ (row & 7)) << 4)) = v;
        }
    }
    __syncthreads();

    // fragment smem addresses (lane-constant parts)
    const int arow_f = wm * 32 + (lane & 15);          // + mi*16
    const int achk_f = (lane >> 4);                    // + sp*4 + kk*2
    const int nl = (lane & 7) + ((lane >> 4) << 3);
    const int kc = (lane >> 3) & 1;
    const int brow_f = wn * 64 + nl;                   // + np*16
    // A loader mapping: warp wid covers rows wid*16..wid*16+15
    const int l_cl = lane & 3;

    for (int mb = 0; mb < MCHUNK; mb++) {
        const int m0 = (blockIdx.y * MCHUNK + mb) * 128;

        float d[2][8][4];
        #pragma unroll
        for (int i = 0; i < 2; i++)
            #pragma unroll
            for (int j = 0; j < 8; j++)
                #pragma unroll
                for (int q = 0; q < 4; q++) d[i][j][q] = 0.0f;

        uint4 pf[4];
        // prefetch stage 0
        #pragma unroll
        for (int i = 0; i < 4; i++) {
            int r = i * 8 + (lane >> 2);
            int row_in = r >> 1, half = r & 1;
            int eoff = (m0 + wid * 16 + row_in) * Astride
                     + (half ? Alo_off : Ahi_off) + l_cl * 8;
            pf[i] = *(const uint4*)(A + (size_t)eoff);
        }

        #pragma unroll 1
        for (int s = 0; s < KSTEPS; s++) {
            // store prefetched stage s
            #pragma unroll
            for (int i = 0; i < 4; i++) {
                int r = i * 8 + (lane >> 2);
                int row_in = r >> 1, half = r & 1;
                int row = wid * 16 + row_in;
                int chunk = half * 4 + l_cl;
                *(uint4*)(smem + BSMEM + row * 128 + ((chunk ^ (row & 7)) << 4)) = pf[i];
            }
            __syncthreads();
            // prefetch stage s+1
            if (s + 1 < KSTEPS) {
                #pragma unroll
                for (int i = 0; i < 4; i++) {
                    int r = i * 8 + (lane >> 2);
                    int row_in = r >> 1, half = r & 1;
                    int eoff = (m0 + wid * 16 + row_in) * Astride
                             + (half ? Alo_off : Ahi_off) + (s + 1) * 32 + l_cl * 8;
                    pf[i] = *(const uint4*)(A + (size_t)eoff);
                }
            }
            // MMA on stage s
            #pragma unroll
            for (int kk = 0; kk < 2; kk++) {
                uint32_t a[2][2][4];   // [sp][mi]
                uint32_t b[2][4][4];   // [sp][np]
                #pragma unroll
                for (int sp = 0; sp < 2; sp++)
                    #pragma unroll
                    for (int mi = 0; mi < 2; mi++) {
                        int row = arow_f + mi * 16;
                        int chunk = sp * 4 + kk * 2 + achk_f;
                        LDSM4(a[sp][mi], sA + row * 128 + ((chunk ^ (row & 7)) << 4));
                    }
                #pragma unroll
                for (int sp = 0; sp < 2; sp++)
                    #pragma unroll
                    for (int np = 0; np < 4; np++) {
                        int n = brow_f + np * 16;
                        int chunk = sp * 48 + s * 4 + kk * 2 + kc;
                        LDSM4(b[sp][np], sB + n * 1536 + ((chunk ^ (n & 7)) << 4));
                    }
                #pragma unroll
                for (int mi = 0; mi < 2; mi++)
                    #pragma unroll
                    for (int np = 0; np < 4; np++)
                        #pragma unroll
                        for (int sub = 0; sub < 2; sub++)
                            MMA16816(d[mi][np * 2 + sub], a[0][mi], b[0][np][sub*2], b[0][np][sub*2+1]);
                #pragma unroll
                for (int mi = 0; mi < 2; mi++)
                    #pragma unroll
                    for (int np = 0; np < 4; np++)
                        #pragma unroll
                        for (int sub = 0; sub < 2; sub++)
                            MMA16816(d[mi][np * 2 + sub], a[0][mi], b[1][np][sub*2], b[1][np][sub*2+1]);
                #pragma unroll
                for (int mi = 0; mi < 2; mi++)
                    #pragma unroll
                    for (int np = 0; np < 4; np++)
                        #pragma unroll
                        for (int sub = 0; sub < 2; sub++)
                            MMA16816(d[mi][np * 2 + sub], a[1][mi], b[0][np][sub*2], b[0][np][sub*2+1]);
            }
            __syncthreads();
        }

        // ---- epilogue ----
        #pragma unroll
        for (int mi = 0; mi < 2; mi++) {
            int row0 = m0 + wm * 32 + mi * 16 + (lane >> 2);
            #pragma unroll
            for (int ni = 0; ni < 8; ni++) {
                int col = n0 + wn * 64 + ni * 8 + (lane & 3) * 2;
                if (MODE == 0) {
                    float* o = (float*)out;
                    *(float2*)(o + (size_t)row0 * Ntot + col)       = make_float2(d[mi][ni][0], d[mi][ni][1]);
                    *(float2*)(o + (size_t)(row0 + 8) * Ntot + col) = make_float2(d[mi][ni][2], d[mi][ni][3]);
                } else if (MODE == 1) {
                    float b0 = bias[col], b1 = bias[col + 1];
                    float* o = (float*)out;
                    float2 r0 = *(const float2*)(res + (size_t)row0 * Ntot + col);
                    float2 r1 = *(const float2*)(res + (size_t)(row0 + 8) * Ntot + col);
                    *(float2*)(o + (size_t)row0 * Ntot + col) =
                        make_float2(d[mi][ni][0] + b0 + r0.x, d[mi][ni][1] + b1 + r0.y);
                    *(float2*)(o + (size_t)(row0 + 8) * Ntot + col) =
                        make_float2(d[mi][ni][2] + b0 + r1.x, d[mi][ni][3] + b1 + r1.y);
                } else if (MODE == 2) {
                    float b0 = bias[col], b1 = bias[col + 1];
                    __nv_bfloat16* ob = (__nv_bfloat16*)out;
                    #pragma unroll
                    for (int rr = 0; rr < 2; rr++) {
                        int row = row0 + rr * 8;
                        float v0 = fmaxf(d[mi][ni][2 * rr]     + b0, 0.0f);
                        float v1 = fmaxf(d[mi][ni][2 * rr + 1] + b1, 0.0f);
                        __nv_bfloat16 h0 = bf_hi(v0), h1 = bf_hi(v1);
                        __nv_bfloat16* orow = ob + (size_t)row * (2 * Ntot);
                        *(__nv_bfloat162*)(orow + col)        = __nv_bfloat162(h0, h1);
                        *(__nv_bfloat162*)(orow + Ntot + col) = __nv_bfloat162(bf_lo(v0, h0), bf_lo(v1, h1));
                    }
                } else {  // MODE 3: RMW accumulate
                    float* o = (float*)out;
                    float2 r0 = *(float2*)(o + (size_t)row0 * Ntot + col);
                    float2 r1 = *(float2*)(o + (size_t)(row0 + 8) * Ntot + col);
                    *(float2*)(o + (size_t)row0 * Ntot + col) =
                        make_float2(d[mi][ni][0] + r0.x, d[mi][ni][1] + r0.y);
                    *(float2*)(o + (size_t)(row0 + 8) * Ntot + col) =
                        make_float2(d[mi][ni][2] + r1.x, d[mi][ni][3] + r1.y);
                }
            }
        }
    }
}

// ---------------- attention: online block softmax, 128 thr = 64 rows x 2 halves ----------------
__global__ void __launch_bounds__(128)
attn_kernel(const float* __restrict__ qkv, __nv_bfloat16* __restrict__ out) {
    const int b = blockIdx.x, h = blockIdx.y;
    const int tid = threadIdx.x;
    const int r = tid >> 1, half = tid & 1;
    __shared__ float ks[SEQ][HSZ];
    __shared__ float vs[SEQ][HSZ];

    for (int i = tid; i < SEQ * (HSZ / 4); i += 128) {
        int s = i / (HSZ / 4), c = i % (HSZ / 4);
        const float* src = qkv + (size_t)(b * SEQ + s) * (3 * EMB) + h * HSZ;
        *(float4*)&ks[s][c * 4] = *(const float4*)(src + EMB + c * 4);
        *(float4*)&vs[s][c * 4] = *(const float4*)(src + 2 * EMB + c * 4);
    }
    float q[24];
    {
        const float* qsrc = qkv + (size_t)(b * SEQ + r) * (3 * EMB) + h * HSZ + half * 24;
        #pragma unroll
        for (int i = 0; i < 6; i++) {
            float4 v = *(const float4*)(qsrc + 4 * i);
            q[4*i] = v.x; q[4*i+1] = v.y; q[4*i+2] = v.z; q[4*i+3] = v.w;
        }
    }
    __syncthreads();

    const uint32_t pmask = 3u << ((tid & 31) & ~1);
    float m = -1e30f, l = 0.0f;
    float o[24];
    #pragma unroll
    for (int dd = 0; dd < 24; dd++) o[dd] = 0.0f;

    for (int s0 = 0; s0 <= r; s0 += 16) {
        float sc[16];
        float bm = -1e30f;
        #pragma unroll
        for (int j = 0; j < 16; j++) {
            int s = s0 + j;
            float pd = 0.0f;
            if (s <= r) {
                const float* kp = &ks[s][half * 24];
                #pragma unroll
                for (int dd = 0; dd < 24; dd++) pd += q[dd] * kp[dd];
            }
            pd += __shfl_xor_sync(pmask, pd, 1);
            sc[j] = (s <= r) ? pd * ATT_SCALE : -1e30f;
            bm = fmaxf(bm, sc[j]);
        }
        float nm = fmaxf(m, bm);
        float alpha = __expf(m - nm);
        l *= alpha;
        #pragma unroll
        for (int dd = 0; dd < 24; dd++) o[dd] *= alpha;
        #pragma unroll
        for (int j = 0; j < 16; j++) {
            float p = __expf(sc[j] - nm);
            l += p;
            int sv = s0 + j; sv = sv < SEQ ? sv : SEQ - 1;
            const float* vp = &vs[sv][half * 24];
            #pragma unroll
            for (int dd = 0; dd < 24; dd++) o[dd] += p * vp[dd];
        }
        m = nm;
    }
    float inv = 1.0f / l;
    __nv_bfloat16* op = out + (size_t)(b * SEQ + r) * (2 * EMB) + h * HSZ + half * 24;
    #pragma unroll
    for (int i = 0; i < 12; i++) {
        float v0 = o[2*i] * inv, v1 = o[2*i+1] * inv;
        __nv_bfloat16 h0 = bf_hi(v0), h1 = bf_hi(v1);
        *(__nv_bfloat162*)(op + 2*i)       = __nv_bfloat162(h0, h1);
        *(__nv_bfloat162*)(op + EMB + 2*i) = __nv_bfloat162(bf_lo(v0, h0), bf_lo(v1, h1));
    }
}

// ---------------- launch ----------------
extern "C" void kernel_launch(void* const* d_in, const int* in_sizes, int n_in,
                              void* d_out, int out_size) {
    const float* x     = (const float*)d_in[0];
    const float* ln1_g = (const float*)d_in[1];
    const float* ln1_b = (const float*)d_in[2];
    const float* ln2_g = (const float*)d_in[3];
    const float* ln2_b = (const float*)d_in[4];
    const float* Wq    = (const float*)d_in[5];
    const float* Wk    = (const float*)d_in[6];
    const float* Wv    = (const float*)d_in[7];
    const float* Wp    = (const float*)d_in[8];
    const float* bp    = (const float*)d_in[9];
    const float* W1    = (const float*)d_in[10];
    const float* b1    = (const float*)d_in[11];
    const float* W2    = (const float*)d_in[12];
    const float* b2    = (const float*)d_in[13];
    float* out = (float*)d_out;

    __nv_bfloat16 *ln1, *attn, *h2, *hid, *wqkv, *wp, *w1, *w2;
    float *qkv, *x2;
    cudaGetSymbolAddress((void**)&ln1,  g_ln1);
    cudaGetSymbolAddress((void**)&qkv,  g_qkv);
    cudaGetSymbolAddress((void**)&attn, g_attn);
    cudaGetSymbolAddress((void**)&x2,   g_x2);
    cudaGetSymbolAddress((void**)&h2,   g_h2);
    cudaGetSymbolAddress((void**)&hid,  g_hid);
    cudaGetSymbolAddress((void**)&wqkv, g_wqkv);
    cudaGetSymbolAddress((void**)&wp,   g_wp);
    cudaGetSymbolAddress((void**)&w1,   g_w1);
    cudaGetSymbolAddress((void**)&w2,   g_w2);

    cudaFuncSetAttribute(gemm_tc<0>, cudaFuncAttributeMaxDynamicSharedMemorySize, GSMEM);
    cudaFuncSetAttribute(gemm_tc<1>, cudaFuncAttributeMaxDynamicSharedMemorySize, GSMEM);
    cudaFuncSetAttribute(gemm_tc<2>, cudaFuncAttributeMaxDynamicSharedMemorySize, GSMEM);
    cudaFuncSetAttribute(gemm_tc<3>, cudaFuncAttributeMaxDynamicSharedMemorySize, GSMEM);

    // weight prep
    prep_wqkv_kernel<<<(NHEAD * EMB * HSZ + 255) / 256, 256>>>(Wq, Wk, Wv);
    prep_w_kernel<<<(EMB * EMB + 255) / 256, 256>>>(Wp, wp, EMB, EMB);
    prep_w_kernel<<<(EMB * FF + 255) / 256, 256>>>(W1, w1, EMB, FF);
    prep_w_kernel<<<(FF * EMB + 255) / 256, 256>>>(W2, w2, FF, EMB);

    const dim3 gQKV(9, 64), gP(3, 64), gM1(12, 64), gM2(3, 64);

    // 1) LN1 -> split bf16
    ln_split_kernel<<<N_TOK, 96>>>(x, ln1_g, ln1_b, ln1);
    // 2) QKV GEMM -> fp32 qkv
    gemm_tc<0><<<gQKV, 256, GSMEM>>>(ln1, 2*EMB, 0, EMB, wqkv, 2*EMB, 0, EMB,
                                     nullptr, nullptr, qkv, 3*EMB);
    // 3) attention -> split bf16
    attn_kernel<<<dim3(2048, NHEAD), 128>>>(qkv, attn);
    // 4) proj + bias + residual(x) -> fp32 x2
    gemm_tc<1><<<gP, 256, GSMEM>>>(attn, 2*EMB, 0, EMB, wp, 2*EMB, 0, EMB,
                                   bp, x, x2, EMB);
    // 5) LN2 -> split bf16
    ln_split_kernel<<<N_TOK, 96>>>(x2, ln2_g, ln2_b, h2);
    // 6) MLP up + relu -> split bf16 hidden
    gemm_tc<2><<<gM1, 256, GSMEM>>>(h2, 2*EMB, 0, EMB, w1, 2*EMB, 0, EMB,
                                    b1, nullptr, hid, FF);
    // 7) MLP down: 4 sequential K-chunks of 384
    gemm_tc<1><<<gM2, 256, GSMEM>>>(hid, 2*FF, 0, FF, w2, 2*FF, 0, FF,
                                    b2, x2, out, EMB);
    for (int c = 1; c < 4; c++) {
        gemm_tc<3><<<gM2, 256, GSMEM>>>(hid, 2*FF, c*EMB, FF + c*EMB,
                                        w2, 2*FF, c*EMB, FF + c*EMB,
                                        nullptr, nullptr, out, EMB);
    }
}

// round 6
// speedup vs baseline: 1.5664x; 1.5664x over previous
#include <cuda_runtime.h>
#include <cuda_bf16.h>
#include <cuda_fp16.h>
#include <cstdint>

// ---------------- problem constants ----------------
constexpr int N_TOK  = 2048 * 64;   // 131072 tokens
constexpr int EMB    = 384;
constexpr int NHEAD  = 8;
constexpr int HSZ    = 48;
constexpr int SEQ    = 64;
constexpr int FF     = 1536;
constexpr float ATT_SCALE = 2.449489742783178f;

// ---------------- scratch (static device memory) ----------------
__device__ __align__(128) __nv_bfloat16 g_ln1 [(size_t)N_TOK * 2 * EMB];   // [hi|lo] for QKV
__device__ __align__(128) float         g_qkv [(size_t)N_TOK * 3 * EMB];   // fp32 q|k|v
__device__ __align__(128) __half        g_attnh[(size_t)N_TOK * EMB];      // fp16
__device__ __align__(128) float         g_x2  [(size_t)N_TOK * EMB];       // fp32 residual
__device__ __align__(128) __half        g_h2h [(size_t)N_TOK * EMB];       // fp16
__device__ __align__(128) __half        g_hidh[(size_t)N_TOK * FF];        // fp16
__device__ __align__(128) __nv_bfloat16 g_wqkv[(size_t)(3*EMB) * 2 * EMB]; // [N][2K] hi|lo
__device__ __align__(128) __half        g_wph [(size_t)EMB * EMB];         // [N][K] fp16
__device__ __align__(128) __half        g_w1h [(size_t)FF  * EMB];
__device__ __align__(128) __half        g_w2h [(size_t)EMB * FF];

// ---------------- PTX helpers ----------------
__device__ __forceinline__ uint32_t smem_u32(const void* p) {
    uint32_t a;
    asm("{ .reg .u64 t; cvta.to.shared.u64 t, %1; cvt.u32.u64 %0, t; }" : "=r"(a) : "l"(p));
    return a;
}
#define CPASYNC16(dst, src) asm volatile("cp.async.cg.shared.global [%0], [%1], 16;" :: "r"(dst), "l"(src) : "memory")
#define CP_COMMIT()         asm volatile("cp.async.commit_group;" ::: "memory")
#define CP_WAIT1()          asm volatile("cp.async.wait_group 1;" ::: "memory")

#define LDSM4(r, addr) \
    asm volatile("ldmatrix.sync.aligned.m8n8.x4.shared.b16 {%0,%1,%2,%3}, [%4];" \
        : "=r"((r)[0]), "=r"((r)[1]), "=r"((r)[2]), "=r"((r)[3]) : "r"(addr))

#define MMA_BF16(d, a, b0, b1) \
    asm volatile("mma.sync.aligned.m16n8k16.row.col.f32.bf16.bf16.f32 " \
        "{%0,%1,%2,%3}, {%4,%5,%6,%7}, {%8,%9}, {%0,%1,%2,%3};" \
        : "+f"((d)[0]), "+f"((d)[1]), "+f"((d)[2]), "+f"((d)[3]) \
        : "r"((a)[0]), "r"((a)[1]), "r"((a)[2]), "r"((a)[3]), "r"(b0), "r"(b1))

#define MMA_FP16(d, a, b0, b1) \
    asm volatile("mma.sync.aligned.m16n8k16.row.col.f32.f16.f16.f32 " \
        "{%0,%1,%2,%3}, {%4,%5,%6,%7}, {%8,%9}, {%0,%1,%2,%3};" \
        : "+f"((d)[0]), "+f"((d)[1]), "+f"((d)[2]), "+f"((d)[3]) \
        : "r"((a)[0]), "r"((a)[1]), "r"((a)[2]), "r"((a)[3]), "r"(b0), "r"(b1))

__device__ __forceinline__ __nv_bfloat16 bf_hi(float v) { return __float2bfloat16(v); }
__device__ __forceinline__ __nv_bfloat16 bf_lo(float v, __nv_bfloat16 hi) {
    return __float2bfloat16(v - __bfloat162float(hi));
}

// ---------------- weight prep ----------------
// W [K][N] fp32 -> out [N][Kfull] fp16 (transpose)
__global__ void prep_w_fp16(const float* __restrict__ W, __half* __restrict__ out,
                            int K, int N, int Kfull) {
    int i = blockIdx.x * blockDim.x + threadIdx.x;
    if (i >= K * N) return;
    int k = i / N, n = i % N;
    out[(size_t)n * Kfull + k] = __float2half(W[i]);
}
__global__ void prep_wqkv_kernel(const float* __restrict__ Wq, const float* __restrict__ Wk,
                                 const float* __restrict__ Wv) {
    int i = blockIdx.x * blockDim.x + threadIdx.x;
    if (i >= NHEAD * EMB * HSZ) return;
    int h = i / (EMB * HSZ), r = i % (EMB * HSZ), c = r / HSZ, d = r % HSZ;
    int n = h * HSZ + d;
    float q = Wq[i], k = Wk[i], v = Wv[i];
    __nv_bfloat16 qh = bf_hi(q), kh = bf_hi(k), vh = bf_hi(v);
    size_t rq = (size_t)n * 2 * EMB, rk = (size_t)(EMB + n) * 2 * EMB, rv = (size_t)(2 * EMB + n) * 2 * EMB;
    g_wqkv[rq + c] = qh;  g_wqkv[rq + EMB + c] = bf_lo(q, qh);
    g_wqkv[rk + c] = kh;  g_wqkv[rk + EMB + c] = bf_lo(k, kh);
    g_wqkv[rv + c] = vh;  g_wqkv[rv + EMB + c] = bf_lo(v, vh);
}

// ---------------- layernorm variants ----------------
template<int OUT>  // 0: split bf16 hi/lo  1: fp16
__global__ void ln_kernel(const float* __restrict__ in, const float* __restrict__ g,
                          const float* __restrict__ b, void* __restrict__ outp) {
    int row = blockIdx.x;
    int t = threadIdx.x;  // 0..95
    float4 v = ((const float4*)(in + (size_t)row * EMB))[t];
    float s  = v.x + v.y + v.z + v.w;
    float ss = v.x * v.x + v.y * v.y + v.z * v.z + v.w * v.w;
    #pragma unroll
    for (int off = 16; off > 0; off >>= 1) {
        s  += __shfl_down_sync(0xffffffffu, s, off);
        ss += __shfl_down_sync(0xffffffffu, ss, off);
    }
    __shared__ float red0[3], red1[3];
    int w = t >> 5, l = t & 31;
    if (l == 0) { red0[w] = s; red1[w] = ss; }
    __syncthreads();
    float S = red0[0] + red0[1] + red0[2];
    float SS = red1[0] + red1[1] + red1[2];
    float mu = S * (1.0f / EMB);
    float var = SS * (1.0f / EMB) - mu * mu;
    float rs = rsqrtf(var + 1e-5f);
    float4 gv = ((const float4*)g)[t];
    float4 bv = ((const float4*)b)[t];
    float o[4] = {(v.x - mu) * rs * gv.x + bv.x, (v.y - mu) * rs * gv.y + bv.y,
                  (v.z - mu) * rs * gv.z + bv.z, (v.w - mu) * rs * gv.w + bv.w};
    if (OUT == 0) {
        __nv_bfloat16* orow = (__nv_bfloat16*)outp + (size_t)row * 2 * EMB;
        __nv_bfloat162 hi2[2], lo2[2];
        #pragma unroll
        for (int j = 0; j < 2; j++) {
            __nv_bfloat16 h0 = bf_hi(o[2 * j]), h1 = bf_hi(o[2 * j + 1]);
            hi2[j] = __nv_bfloat162(h0, h1);
            lo2[j] = __nv_bfloat162(bf_lo(o[2 * j], h0), bf_lo(o[2 * j + 1], h1));
        }
        *(uint2*)(orow + 4 * t)       = *(uint2*)hi2;
        *(uint2*)(orow + EMB + 4 * t) = *(uint2*)lo2;
    } else {
        __half* orow = (__half*)outp + (size_t)row * EMB;
        __half2 h2[2] = {__floats2half2_rn(o[0], o[1]), __floats2half2_rn(o[2], o[3])};
        *(uint2*)(orow + 4 * t) = *(uint2*)h2;
    }
}

// ================= 3-pass bf16 GEMM (QKV only) — round-4 proven =================
constexpr int PIECE  = 128 * 144;
constexpr int STAGE3 = 4 * PIECE;
constexpr int GSMEM3 = 3 * STAGE3;       // 221184

__global__ void __launch_bounds__(256, 1)
gemm_bf3(const __nv_bfloat16* __restrict__ A, const __nv_bfloat16* __restrict__ B,
         float* __restrict__ out, int Kw, int Ntot) {
    extern __shared__ char smem[];
    const uint32_t sbase = smem_u32(smem);
    const int tid = threadIdx.x, lane = tid & 31, wid = tid >> 5;
    const int wm = wid >> 1, wn = wid & 1;
    const int m0 = blockIdx.y * 128, n0 = blockIdx.x * 128;
    const int nstages = Kw >> 6;

    const int lrow = tid >> 1, lhalf = tid & 1;
    const __nv_bfloat16* agp = A + (size_t)(m0 + lrow) * (2 * Kw) + lhalf * 32;
    const __nv_bfloat16* bgp = B + (size_t)(n0 + lrow) * (2 * Kw) + lhalf * 32;
    const uint32_t ldst = (uint32_t)(lrow * 144 + lhalf * 64);

#define LOAD_STAGE3(bufi, k0v) do { \
        const uint32_t sb = sbase + (bufi) * STAGE3; \
        const __nv_bfloat16* a0p = agp + (k0v); \
        const __nv_bfloat16* b0p = bgp + (k0v); \
        uint32_t d0 = sb + ldst; \
        CPASYNC16(d0 +  0, a0p);      CPASYNC16(d0 + 16, a0p + 8); \
        CPASYNC16(d0 + 32, a0p + 16); CPASYNC16(d0 + 48, a0p + 24); \
        d0 += PIECE; a0p += Kw; \
        CPASYNC16(d0 +  0, a0p);      CPASYNC16(d0 + 16, a0p + 8); \
        CPASYNC16(d0 + 32, a0p + 16); CPASYNC16(d0 + 48, a0p + 24); \
        d0 = sb + 2 * PIECE + ldst; \
        CPASYNC16(d0 +  0, b0p);      CPASYNC16(d0 + 16, b0p + 8); \
        CPASYNC16(d0 + 32, b0p + 16); CPASYNC16(d0 + 48, b0p + 24); \
        d0 += PIECE; b0p += Kw; \
        CPASYNC16(d0 +  0, b0p);      CPASYNC16(d0 + 16, b0p + 8); \
        CPASYNC16(d0 + 32, b0p + 16); CPASYNC16(d0 + 48, b0p + 24); \
    } while (0)

    float d[2][8][4];
    #pragma unroll
    for (int i = 0; i < 2; i++)
        #pragma unroll
        for (int j = 0; j < 8; j++)
            #pragma unroll
            for (int q = 0; q < 4; q++) d[i][j][q] = 0.0f;

    const uint32_t a_off = (uint32_t)((wm * 32 + (lane & 15)) * 144 + (lane >> 4) * 16);
    const int nl = (lane & 7) + ((lane >> 4) << 3);
    const int kc = (lane >> 3) & 1;
    const uint32_t b_off = (uint32_t)((wn * 64 + nl) * 144 + kc * 16);

    LOAD_STAGE3(0, 0);  CP_COMMIT();
    LOAD_STAGE3(1, 64); CP_COMMIT();

    for (int it = 0; it < nstages; it++) {
        CP_WAIT1();
        __syncthreads();
        if (it + 2 < nstages) LOAD_STAGE3((it + 2) % 3, (it + 2) * 64);
        CP_COMMIT();

        const uint32_t sA = sbase + (it % 3) * STAGE3;
        const uint32_t sB = sA + 2 * PIECE;
        #pragma unroll
        for (int kk = 0; kk < 4; kk++) {
            uint32_t a[2][2][4];
            uint32_t b[2][4][4];
            #pragma unroll
            for (int sp = 0; sp < 2; sp++)
                #pragma unroll
                for (int mi = 0; mi < 2; mi++)
                    LDSM4(a[sp][mi], sA + sp * PIECE + a_off + mi * (16 * 144) + kk * 32);
            #pragma unroll
            for (int sp = 0; sp < 2; sp++)
                #pragma unroll
                for (int np = 0; np < 4; np++)
                    LDSM4(b[sp][np], sB + sp * PIECE + b_off + np * (16 * 144) + kk * 32);
            #pragma unroll
            for (int mi = 0; mi < 2; mi++)
                #pragma unroll
                for (int np = 0; np < 4; np++)
                    #pragma unroll
                    for (int sub = 0; sub < 2; sub++)
                        MMA_BF16(d[mi][np * 2 + sub], a[0][mi], b[0][np][sub*2], b[0][np][sub*2+1]);
            #pragma unroll
            for (int mi = 0; mi < 2; mi++)
                #pragma unroll
                for (int np = 0; np < 4; np++)
                    #pragma unroll
                    for (int sub = 0; sub < 2; sub++)
                        MMA_BF16(d[mi][np * 2 + sub], a[0][mi], b[1][np][sub*2], b[1][np][sub*2+1]);
            #pragma unroll
            for (int mi = 0; mi < 2; mi++)
                #pragma unroll
                for (int np = 0; np < 4; np++)
                    #pragma unroll
                    for (int sub = 0; sub < 2; sub++)
                        MMA_BF16(d[mi][np * 2 + sub], a[1][mi], b[0][np][sub*2], b[0][np][sub*2+1]);
        }
    }
#undef LOAD_STAGE3

    #pragma unroll
    for (int mi = 0; mi < 2; mi++) {
        int row0 = m0 + wm * 32 + mi * 16 + (lane >> 2);
        #pragma unroll
        for (int ni = 0; ni < 8; ni++) {
            int col = n0 + wn * 64 + ni * 8 + (lane & 3) * 2;
            *(float2*)(out + (size_t)row0 * Ntot + col)       = make_float2(d[mi][ni][0], d[mi][ni][1]);
            *(float2*)(out + (size_t)(row0 + 8) * Ntot + col) = make_float2(d[mi][ni][2], d[mi][ni][3]);
        }
    }
}

// ================= 1-pass fp16 B-resident GEMM (proj / MLP) =================
// C[M,128] = A[M,K=384] @ B[128,K=384]^T, fp16 operands, fp32 accum.
// B resident (96KB, XOR-swizzled 768B rows); A 3-slot cp.async ring (16KB/slot).
// MCHUNK=16 M-blocks per CTA, pipeline flows across block boundaries.
constexpr int BRES   = 128 * 768;             // 98304
constexpr int ASLOT  = 128 * 128;             // 16384
constexpr int GSMEMF = BRES + 3 * ASLOT;      // 147456
constexpr int KST    = 6;                     // K = 384 / 64
constexpr int MCHUNK = 16;

template<int MODE>  // 1: fp32 out = acc+bias+res   2: fp16 out = relu(acc+bias)   3: fp32 out += acc
__global__ void __launch_bounds__(256, 1)
gemm_f16(const __half* __restrict__ A, int Astride, int Aoff,
         const __half* __restrict__ B, int Bstride, int Boff,
         const float* __restrict__ bias, const float* __restrict__ res,
         void* __restrict__ out, int Ntot) {
    extern __shared__ char smem[];
    const uint32_t sB = smem_u32(smem);
    const uint32_t sA0 = sB + BRES;
    const int tid = threadIdx.x, lane = tid & 31, wid = tid >> 5;
    const int wm = wid >> 1, wn = wid & 1;
    const int n0 = blockIdx.x * 128;

    // ---- one-time B load: 128 rows x 48 chunks ----
    {
        #pragma unroll 4
        for (int i = 0; i < 24; i++) {
            int cg = i * 256 + tid;
            int row = cg / 48, c = cg - row * 48;
            const __half* src = B + (size_t)(n0 + row) * Bstride + Boff + c * 8;
            uint4 v = *(const uint4*)src;
            *(uint4*)(smem + row * 768 + ((c ^ (row & 7)) << 4)) = v;
        }
    }

    // A loader mapping: thread -> (row = tid>>1, half = tid&1), 4 chunks of 16B
    const int lrow = tid >> 1, lhalf = tid & 1;
    const uint32_t aswz = (uint32_t)(lrow & 7);

#define LOAD_A(gidx) do { \
        int _mb = (gidx) / KST, _s = (gidx) - _mb * KST; \
        const __half* _src = A + (size_t)((blockIdx.y * MCHUNK + _mb) * 128 + lrow) * Astride \
                           + Aoff + _s * 64 + lhalf * 32; \
        uint32_t _dst = sA0 + ((gidx) % 3) * ASLOT + (uint32_t)(lrow * 128); \
        CPASYNC16(_dst + (((lhalf * 4 + 0) ^ aswz) << 4), _src); \
        CPASYNC16(_dst + (((lhalf * 4 + 1) ^ aswz) << 4), _src + 8); \
        CPASYNC16(_dst + (((lhalf * 4 + 2) ^ aswz) << 4), _src + 16); \
        CPASYNC16(_dst + (((lhalf * 4 + 3) ^ aswz) << 4), _src + 24); \
    } while (0)

    // fragment index helpers
    const int arow0 = wm * 32 + (lane & 15);     // + mi*16
    const int achk0 = (lane >> 4);               // + kk*2
    const int nl = (lane & 7) + ((lane >> 4) << 3);
    const int kc = (lane >> 3) & 1;
    const int brow0 = wn * 64 + nl;              // + np*16

    LOAD_A(0); CP_COMMIT();
    LOAD_A(1); CP_COMMIT();
    __syncthreads();   // B resident ready (covered also by pipeline syncs)

    constexpr int G = MCHUNK * KST;
    for (int mb = 0; mb < MCHUNK; mb++) {
        float d[2][8][4];
        #pragma unroll
        for (int i = 0; i < 2; i++)
            #pragma unroll
            for (int j = 0; j < 8; j++)
                #pragma unroll
                for (int q = 0; q < 4; q++) d[i][j][q] = 0.0f;

        for (int s = 0; s < KST; s++) {
            const int g = mb * KST + s;
            CP_WAIT1();
            __syncthreads();
            if (g + 2 < G) LOAD_A(g + 2);
            CP_COMMIT();

            const uint32_t sA = sA0 + (g % 3) * ASLOT;
            #pragma unroll
            for (int kk = 0; kk < 4; kk++) {
                uint32_t a[2][4];
                uint32_t b[4][4];
                #pragma unroll
                for (int mi = 0; mi < 2; mi++) {
                    int row = arow0 + mi * 16;
                    int chunk = kk * 2 + achk0;
                    LDSM4(a[mi], sA + row * 128 + ((chunk ^ (row & 7)) << 4));
                }
                #pragma unroll
                for (int np = 0; np < 4; np++) {
                    int n = brow0 + np * 16;
                    int chunk = s * 8 + kk * 2 + kc;
                    LDSM4(b[np], sB + n * 768 + ((chunk ^ (n & 7)) << 4));
                }
                #pragma unroll
                for (int mi = 0; mi < 2; mi++)
                    #pragma unroll
                    for (int np = 0; np < 4; np++)
                        #pragma unroll
                        for (int sub = 0; sub < 2; sub++)
                            MMA_FP16(d[mi][np * 2 + sub], a[mi], b[np][sub*2], b[np][sub*2+1]);
            }
        }

        // ---- epilogue for this M-block ----
        const int m0 = (blockIdx.y * MCHUNK + mb) * 128;
        #pragma unroll
        for (int mi = 0; mi < 2; mi++) {
            int row0 = m0 + wm * 32 + mi * 16 + (lane >> 2);
            #pragma unroll
            for (int ni = 0; ni < 8; ni++) {
                int col = n0 + wn * 64 + ni * 8 + (lane & 3) * 2;
                if (MODE == 1) {
                    float b0 = bias[col], b1 = bias[col + 1];
                    float* o = (float*)out;
                    float2 r0 = *(const float2*)(res + (size_t)row0 * Ntot + col);
                    float2 r1 = *(const float2*)(res + (size_t)(row0 + 8) * Ntot + col);
                    *(float2*)(o + (size_t)row0 * Ntot + col) =
                        make_float2(d[mi][ni][0] + b0 + r0.x, d[mi][ni][1] + b1 + r0.y);
                    *(float2*)(o + (size_t)(row0 + 8) * Ntot + col) =
                        make_float2(d[mi][ni][2] + b0 + r1.x, d[mi][ni][3] + b1 + r1.y);
                } else if (MODE == 2) {
                    float b0 = bias[col], b1 = bias[col + 1];
                    __half* ob = (__half*)out;
                    *(__half2*)(ob + (size_t)row0 * Ntot + col) =
                        __floats2half2_rn(fmaxf(d[mi][ni][0] + b0, 0.0f), fmaxf(d[mi][ni][1] + b1, 0.0f));
                    *(__half2*)(ob + (size_t)(row0 + 8) * Ntot + col) =
                        __floats2half2_rn(fmaxf(d[mi][ni][2] + b0, 0.0f), fmaxf(d[mi][ni][3] + b1, 0.0f));
                } else {  // MODE 3: accumulate
                    float* o = (float*)out;
                    float2 r0 = *(float2*)(o + (size_t)row0 * Ntot + col);
                    float2 r1 = *(float2*)(o + (size_t)(row0 + 8) * Ntot + col);
                    *(float2*)(o + (size_t)row0 * Ntot + col) =
                        make_float2(d[mi][ni][0] + r0.x, d[mi][ni][1] + r0.y);
                    *(float2*)(o + (size_t)(row0 + 8) * Ntot + col) =
                        make_float2(d[mi][ni][2] + r1.x, d[mi][ni][3] + r1.y);
                }
            }
        }
    }
#undef LOAD_A
}

// ---------------- attention (fp32 in, fp16 out) ----------------
__global__ void __launch_bounds__(128)
attn_kernel(const float* __restrict__ qkv, __half* __restrict__ out) {
    const int b = blockIdx.x, h = blockIdx.y;
    const int tid = threadIdx.x;
    const int r = tid >> 1, half = tid & 1;
    __shared__ float ks[SEQ][HSZ];
    __shared__ float vs[SEQ][HSZ];

    for (int i = tid; i < SEQ * (HSZ / 4); i += 128) {
        int s = i / (HSZ / 4), c = i % (HSZ / 4);
        const float* src = qkv + (size_t)(b * SEQ + s) * (3 * EMB) + h * HSZ;
        *(float4*)&ks[s][c * 4] = *(const float4*)(src + EMB + c * 4);
        *(float4*)&vs[s][c * 4] = *(const float4*)(src + 2 * EMB + c * 4);
    }
    float q[24];
    {
        const float* qsrc = qkv + (size_t)(b * SEQ + r) * (3 * EMB) + h * HSZ + half * 24;
        #pragma unroll
        for (int i = 0; i < 6; i++) {
            float4 v = *(const float4*)(qsrc + 4 * i);
            q[4*i] = v.x; q[4*i+1] = v.y; q[4*i+2] = v.z; q[4*i+3] = v.w;
        }
    }
    __syncthreads();

    const uint32_t pmask = 3u << ((tid & 31) & ~1);
    float m = -1e30f, l = 0.0f;
    float o[24];
    #pragma unroll
    for (int dd = 0; dd < 24; dd++) o[dd] = 0.0f;

    for (int s0 = 0; s0 <= r; s0 += 16) {
        float sc[16];
        float bm = -1e30f;
        #pragma unroll
        for (int j = 0; j < 16; j++) {
            int s = s0 + j;
            float pd = 0.0f;
            if (s <= r) {
                const float* kp = &ks[s][half * 24];
                #pragma unroll
                for (int dd = 0; dd < 24; dd++) pd += q[dd] * kp[dd];
            }
            pd += __shfl_xor_sync(pmask, pd, 1);
            sc[j] = (s <= r) ? pd * ATT_SCALE : -1e30f;
            bm = fmaxf(bm, sc[j]);
        }
        float nm = fmaxf(m, bm);
        float alpha = __expf(m - nm);
        l *= alpha;
        #pragma unroll
        for (int dd = 0; dd < 24; dd++) o[dd] *= alpha;
        #pragma unroll
        for (int j = 0; j < 16; j++) {
            float p = __expf(sc[j] - nm);
            l += p;
            int sv = s0 + j; sv = sv < SEQ ? sv : SEQ - 1;
            const float* vp = &vs[sv][half * 24];
            #pragma unroll
            for (int dd = 0; dd < 24; dd++) o[dd] += p * vp[dd];
        }
        m = nm;
    }
    float inv = 1.0f / l;
    __half* op = out + (size_t)(b * SEQ + r) * EMB + h * HSZ + half * 24;
    #pragma unroll
    for (int i = 0; i < 12; i++)
        *(__half2*)(op + 2 * i) = __floats2half2_rn(o[2*i] * inv, o[2*i+1] * inv);
}

// ---------------- launch ----------------
extern "C" void kernel_launch(void* const* d_in, const int* in_sizes, int n_in,
                              void* d_out, int out_size) {
    const float* x     = (const float*)d_in[0];
    const float* ln1_g = (const float*)d_in[1];
    const float* ln1_b = (const float*)d_in[2];
    const float* ln2_g = (const float*)d_in[3];
    const float* ln2_b = (const float*)d_in[4];
    const float* Wq    = (const float*)d_in[5];
    const float* Wk    = (const float*)d_in[6];
    const float* Wv    = (const float*)d_in[7];
    const float* Wp    = (const float*)d_in[8];
    const float* bp    = (const float*)d_in[9];
    const float* W1    = (const float*)d_in[10];
    const float* b1    = (const float*)d_in[11];
    const float* W2    = (const float*)d_in[12];
    const float* b2    = (const float*)d_in[13];
    float* out = (float*)d_out;

    __nv_bfloat16 *ln1, *wqkv;
    __half *attnh, *h2h, *hidh, *wph, *w1h, *w2h;
    float *qkv, *x2;
    cudaGetSymbolAddress((void**)&ln1,   g_ln1);
    cudaGetSymbolAddress((void**)&qkv,   g_qkv);
    cudaGetSymbolAddress((void**)&attnh, g_attnh);
    cudaGetSymbolAddress((void**)&x2,    g_x2);
    cudaGetSymbolAddress((void**)&h2h,   g_h2h);
    cudaGetSymbolAddress((void**)&hidh,  g_hidh);
    cudaGetSymbolAddress((void**)&wqkv,  g_wqkv);
    cudaGetSymbolAddress((void**)&wph,   g_wph);
    cudaGetSymbolAddress((void**)&w1h,   g_w1h);
    cudaGetSymbolAddress((void**)&w2h,   g_w2h);

    cudaFuncSetAttribute(gemm_bf3,   cudaFuncAttributeMaxDynamicSharedMemorySize, GSMEM3);
    cudaFuncSetAttribute(gemm_f16<1>, cudaFuncAttributeMaxDynamicSharedMemorySize, GSMEMF);
    cudaFuncSetAttribute(gemm_f16<2>, cudaFuncAttributeMaxDynamicSharedMemorySize, GSMEMF);
    cudaFuncSetAttribute(gemm_f16<3>, cudaFuncAttributeMaxDynamicSharedMemorySize, GSMEMF);

    // weight prep
    prep_wqkv_kernel<<<(NHEAD * EMB * HSZ + 255) / 256, 256>>>(Wq, Wk, Wv);
    prep_w_fp16<<<(EMB * EMB + 255) / 256, 256>>>(Wp, wph, EMB, EMB, EMB);
    prep_w_fp16<<<(EMB * FF + 255) / 256, 256>>>(W1, w1h, EMB, FF, EMB);
    prep_w_fp16<<<(FF * EMB + 255) / 256, 256>>>(W2, w2h, FF, EMB, FF);

    // 1) LN1 -> split bf16
    ln_kernel<0><<<N_TOK, 96>>>(x, ln1_g, ln1_b, ln1);
    // 2) QKV GEMM (3-pass bf16) -> fp32 qkv
    gemm_bf3<<<dim3(9, N_TOK / 128), 256, GSMEM3>>>(ln1, wqkv, qkv, EMB, 3 * EMB);
    // 3) attention -> fp16
    attn_kernel<<<dim3(2048, NHEAD), 128>>>(qkv, attnh);
    // 4) proj + bias + residual(x) -> fp32 x2
    gemm_f16<1><<<dim3(3, 64), 256, GSMEMF>>>(attnh, EMB, 0, wph, EMB, 0, bp, x, x2, EMB);
    // 5) LN2 -> fp16
    ln_kernel<1><<<N_TOK, 96>>>(x2, ln2_g, ln2_b, h2h);
    // 6) MLP up + relu -> fp16 hidden
    gemm_f16<2><<<dim3(12, 64), 256, GSMEMF>>>(h2h, EMB, 0, w1h, EMB, 0, b1, nullptr, hidh, FF);
    // 7) MLP down: K=1536 in 4 chunks of 384
    gemm_f16<1><<<dim3(3, 64), 256, GSMEMF>>>(hidh, FF, 0, w2h, FF, 0, b2, x2, out, EMB);
    for (int c = 1; c < 4; c++)
        gemm_f16<3><<<dim3(3, 64), 256, GSMEMF>>>(hidh, FF, c * EMB, w2h, FF, c * EMB,
                                                  nullptr, nullptr, out, EMB);
}

// round 7
// speedup vs baseline: 2.0057x; 1.2804x over previous
#include <cuda_runtime.h>
#include <cuda_bf16.h>
#include <cuda_fp16.h>
#include <cstdint>

// ---------------- problem constants ----------------
constexpr int N_TOK  = 2048 * 64;   // 131072 tokens
constexpr int EMB    = 384;
constexpr int NHEAD  = 8;
constexpr int HSZ    = 48;
constexpr int SEQ    = 64;
constexpr int FF     = 1536;
constexpr float ATT_SCALE = 2.449489742783178f;

// ---------------- scratch (static device memory) ----------------
__device__ __align__(128) __nv_bfloat16 g_ln1 [(size_t)N_TOK * 2 * EMB];    // [hi|lo] for QK
__device__ __align__(128) __half        g_h1h [(size_t)N_TOK * EMB];        // fp16 LN1 (for V)
__device__ __align__(128) float         g_qkv [(size_t)N_TOK * 3 * EMB];    // fp32 q|k|v
__device__ __align__(128) __half        g_attnh[(size_t)N_TOK * EMB];       // fp16
__device__ __align__(128) float         g_x2  [(size_t)N_TOK * EMB];        // fp32 residual
__device__ __align__(128) __half        g_h2h [(size_t)N_TOK * EMB];        // fp16
__device__ __align__(128) __half        g_hidh[(size_t)N_TOK * FF];         // fp16
__device__ __align__(128) __nv_bfloat16 g_wqk [(size_t)(2*EMB) * 2 * EMB];  // [768][hi|lo 768]
__device__ __align__(128) __half        g_wvh [(size_t)EMB * EMB];          // [N][K] fp16
__device__ __align__(128) __half        g_wph [(size_t)EMB * EMB];
__device__ __align__(128) __half        g_w1h [(size_t)FF  * EMB];
__device__ __align__(128) __half        g_w2h [(size_t)EMB * FF];

// ---------------- PTX helpers ----------------
__device__ __forceinline__ uint32_t smem_u32(const void* p) {
    uint32_t a;
    asm("{ .reg .u64 t; cvta.to.shared.u64 t, %1; cvt.u32.u64 %0, t; }" : "=r"(a) : "l"(p));
    return a;
}
#define CPASYNC16(dst, src) asm volatile("cp.async.cg.shared.global [%0], [%1], 16;" :: "r"(dst), "l"(src) : "memory")
#define CP_COMMIT()         asm volatile("cp.async.commit_group;" ::: "memory")
#define CP_WAIT1()          asm volatile("cp.async.wait_group 1;" ::: "memory")

#define LDSM4(r, addr) \
    asm volatile("ldmatrix.sync.aligned.m8n8.x4.shared.b16 {%0,%1,%2,%3}, [%4];" \
        : "=r"((r)[0]), "=r"((r)[1]), "=r"((r)[2]), "=r"((r)[3]) : "r"(addr))

#define MMA_BF16(d, a, b0, b1) \
    asm volatile("mma.sync.aligned.m16n8k16.row.col.f32.bf16.bf16.f32 " \
        "{%0,%1,%2,%3}, {%4,%5,%6,%7}, {%8,%9}, {%0,%1,%2,%3};" \
        : "+f"((d)[0]), "+f"((d)[1]), "+f"((d)[2]), "+f"((d)[3]) \
        : "r"((a)[0]), "r"((a)[1]), "r"((a)[2]), "r"((a)[3]), "r"(b0), "r"(b1))

#define MMA_FP16(d, a, b0, b1) \
    asm volatile("mma.sync.aligned.m16n8k16.row.col.f32.f16.f16.f32 " \
        "{%0,%1,%2,%3}, {%4,%5,%6,%7}, {%8,%9}, {%0,%1,%2,%3};" \
        : "+f"((d)[0]), "+f"((d)[1]), "+f"((d)[2]), "+f"((d)[3]) \
        : "r"((a)[0]), "r"((a)[1]), "r"((a)[2]), "r"((a)[3]), "r"(b0), "r"(b1))

__device__ __forceinline__ __nv_bfloat16 bf_hi(float v) { return __float2bfloat16(v); }
__device__ __forceinline__ __nv_bfloat16 bf_lo(float v, __nv_bfloat16 hi) {
    return __float2bfloat16(v - __bfloat162float(hi));
}

// ---------------- weight prep ----------------
__global__ void prep_w_fp16(const float* __restrict__ W, __half* __restrict__ out,
                            int K, int N, int Kfull) {
    int i = blockIdx.x * blockDim.x + threadIdx.x;
    if (i >= K * N) return;
    int k = i / N, n = i % N;
    out[(size_t)n * Kfull + k] = __float2half(W[i]);
}
// Wq/Wk [H][C][D] -> g_wqk [768][2*384] bf16 split;  Wv -> g_wvh fp16
__global__ void prep_wqkv_kernel(const float* __restrict__ Wq, const float* __restrict__ Wk,
                                 const float* __restrict__ Wv) {
    int i = blockIdx.x * blockDim.x + threadIdx.x;
    if (i >= NHEAD * EMB * HSZ) return;
    int h = i / (EMB * HSZ), r = i % (EMB * HSZ), c = r / HSZ, d = r % HSZ;
    int n = h * HSZ + d;
    float q = Wq[i], k = Wk[i];
    __nv_bfloat16 qh = bf_hi(q), kh = bf_hi(k);
    size_t rq = (size_t)n * 2 * EMB, rk = (size_t)(EMB + n) * 2 * EMB;
    g_wqk[rq + c] = qh;  g_wqk[rq + EMB + c] = bf_lo(q, qh);
    g_wqk[rk + c] = kh;  g_wqk[rk + EMB + c] = bf_lo(k, kh);
    g_wvh[(size_t)n * EMB + c] = __float2half(Wv[i]);
}

// ---------------- layernorm: warp-per-row, 4 rows/block ----------------
template<int MODE>  // 0: bf16 split + fp16   1: fp16 only
__global__ void __launch_bounds__(128)
ln_fused(const float* __restrict__ in, const float* __restrict__ g,
         const float* __restrict__ b, __nv_bfloat16* __restrict__ bfout,
         __half* __restrict__ hout) {
    const int row = blockIdx.x * 4 + (threadIdx.x >> 5);
    const int lane = threadIdx.x & 31;
    const float* rp = in + (size_t)row * EMB + lane * 12;
    float4 v0 = *(const float4*)(rp), v1 = *(const float4*)(rp + 4), v2 = *(const float4*)(rp + 8);
    float vv[12] = {v0.x, v0.y, v0.z, v0.w, v1.x, v1.y, v1.z, v1.w, v2.x, v2.y, v2.z, v2.w};
    float s = 0.0f, ss = 0.0f;
    #pragma unroll
    for (int i = 0; i < 12; i++) { s += vv[i]; ss += vv[i] * vv[i]; }
    #pragma unroll
    for (int off = 16; off > 0; off >>= 1) {
        s  += __shfl_xor_sync(0xffffffffu, s, off);
        ss += __shfl_xor_sync(0xffffffffu, ss, off);
    }
    float mu = s * (1.0f / EMB);
    float var = ss * (1.0f / EMB) - mu * mu;
    float rs = rsqrtf(var + 1e-5f);
    const float* gp = g + lane * 12;
    const float* bp = b + lane * 12;
    float o[12];
    #pragma unroll
    for (int i = 0; i < 12; i++) o[i] = (vv[i] - mu) * rs * gp[i] + bp[i];

    __half hh[12];
    #pragma unroll
    for (int i = 0; i < 12; i++) hh[i] = __float2half(o[i]);
    __half* hrow = hout + (size_t)row * EMB + lane * 12;
    *(uint2*)(hrow)     = *(uint2*)(hh);
    *(uint2*)(hrow + 4) = *(uint2*)(hh + 4);
    *(uint2*)(hrow + 8) = *(uint2*)(hh + 8);

    if (MODE == 0) {
        __nv_bfloat16 hi[12], lo[12];
        #pragma unroll
        for (int i = 0; i < 12; i++) { hi[i] = bf_hi(o[i]); lo[i] = bf_lo(o[i], hi[i]); }
        __nv_bfloat16* orow = bfout + (size_t)row * 2 * EMB + lane * 12;
        *(uint2*)(orow)     = *(uint2*)(hi);
        *(uint2*)(orow + 4) = *(uint2*)(hi + 4);
        *(uint2*)(orow + 8) = *(uint2*)(hi + 8);
        __nv_bfloat16* lrow = orow + EMB;
        *(uint2*)(lrow)     = *(uint2*)(lo);
        *(uint2*)(lrow + 4) = *(uint2*)(lo + 4);
        *(uint2*)(lrow + 8) = *(uint2*)(lo + 8);
    }
}

// ================= 3-pass bf16 GEMM (Q/K only) =================
constexpr int PIECE  = 128 * 144;
constexpr int STAGE3 = 4 * PIECE;
constexpr int GSMEM3 = 3 * STAGE3;       // 221184

__global__ void __launch_bounds__(256, 1)
gemm_bf3(const __nv_bfloat16* __restrict__ A, const __nv_bfloat16* __restrict__ B,
         float* __restrict__ out, int Kw, int Ntot) {
    extern __shared__ char smem[];
    const uint32_t sbase = smem_u32(smem);
    const int tid = threadIdx.x, lane = tid & 31, wid = tid >> 5;
    const int wm = wid >> 1, wn = wid & 1;
    const int m0 = blockIdx.y * 128, n0 = blockIdx.x * 128;
    const int nstages = Kw >> 6;

    const int lrow = tid >> 1, lhalf = tid & 1;
    const __nv_bfloat16* agp = A + (size_t)(m0 + lrow) * (2 * Kw) + lhalf * 32;
    const __nv_bfloat16* bgp = B + (size_t)(n0 + lrow) * (2 * Kw) + lhalf * 32;
    const uint32_t ldst = (uint32_t)(lrow * 144 + lhalf * 64);

#define LOAD_STAGE3(bufi, k0v) do { \
        const uint32_t sb = sbase + (bufi) * STAGE3; \
        const __nv_bfloat16* a0p = agp + (k0v); \
        const __nv_bfloat16* b0p = bgp + (k0v); \
        uint32_t d0 = sb + ldst; \
        CPASYNC16(d0 +  0, a0p);      CPASYNC16(d0 + 16, a0p + 8); \
        CPASYNC16(d0 + 32, a0p + 16); CPASYNC16(d0 + 48, a0p + 24); \
        d0 += PIECE; a0p += Kw; \
        CPASYNC16(d0 +  0, a0p);      CPASYNC16(d0 + 16, a0p + 8); \
        CPASYNC16(d0 + 32, a0p + 16); CPASYNC16(d0 + 48, a0p + 24); \
        d0 = sb + 2 * PIECE + ldst; \
        CPASYNC16(d0 +  0, b0p);      CPASYNC16(d0 + 16, b0p + 8); \
        CPASYNC16(d0 + 32, b0p + 16); CPASYNC16(d0 + 48, b0p + 24); \
        d0 += PIECE; b0p += Kw; \
        CPASYNC16(d0 +  0, b0p);      CPASYNC16(d0 + 16, b0p + 8); \
        CPASYNC16(d0 + 32, b0p + 16); CPASYNC16(d0 + 48, b0p + 24); \
    } while (0)

    float d[2][8][4];
    #pragma unroll
    for (int i = 0; i < 2; i++)
        #pragma unroll
        for (int j = 0; j < 8; j++)
            #pragma unroll
            for (int q = 0; q < 4; q++) d[i][j][q] = 0.0f;

    const uint32_t a_off = (uint32_t)((wm * 32 + (lane & 15)) * 144 + (lane >> 4) * 16);
    const int nl = (lane & 7) + ((lane >> 4) << 3);
    const int kc = (lane >> 3) & 1;
    const uint32_t b_off = (uint32_t)((wn * 64 + nl) * 144 + kc * 16);

    LOAD_STAGE3(0, 0);  CP_COMMIT();
    LOAD_STAGE3(1, 64); CP_COMMIT();

    for (int it = 0; it < nstages; it++) {
        CP_WAIT1();
        __syncthreads();
        if (it + 2 < nstages) LOAD_STAGE3((it + 2) % 3, (it + 2) * 64);
        CP_COMMIT();

        const uint32_t sA = sbase + (it % 3) * STAGE3;
        const uint32_t sB = sA + 2 * PIECE;
        #pragma unroll
        for (int kk = 0; kk < 4; kk++) {
            uint32_t a[2][2][4];
            uint32_t b[2][4][4];
            #pragma unroll
            for (int sp = 0; sp < 2; sp++)
                #pragma unroll
                for (int mi = 0; mi < 2; mi++)
                    LDSM4(a[sp][mi], sA + sp * PIECE + a_off + mi * (16 * 144) + kk * 32);
            #pragma unroll
            for (int sp = 0; sp < 2; sp++)
                #pragma unroll
                for (int np = 0; np < 4; np++)
                    LDSM4(b[sp][np], sB + sp * PIECE + b_off + np * (16 * 144) + kk * 32);
            #pragma unroll
            for (int mi = 0; mi < 2; mi++)
                #pragma unroll
                for (int np = 0; np < 4; np++)
                    #pragma unroll
                    for (int sub = 0; sub < 2; sub++)
                        MMA_BF16(d[mi][np * 2 + sub], a[0][mi], b[0][np][sub*2], b[0][np][sub*2+1]);
            #pragma unroll
            for (int mi = 0; mi < 2; mi++)
                #pragma unroll
                for (int np = 0; np < 4; np++)
                    #pragma unroll
                    for (int sub = 0; sub < 2; sub++)
                        MMA_BF16(d[mi][np * 2 + sub], a[0][mi], b[1][np][sub*2], b[1][np][sub*2+1]);
            #pragma unroll
            for (int mi = 0; mi < 2; mi++)
                #pragma unroll
                for (int np = 0; np < 4; np++)
                    #pragma unroll
                    for (int sub = 0; sub < 2; sub++)
                        MMA_BF16(d[mi][np * 2 + sub], a[1][mi], b[0][np][sub*2], b[0][np][sub*2+1]);
        }
    }
#undef LOAD_STAGE3

    #pragma unroll
    for (int mi = 0; mi < 2; mi++) {
        int row0 = m0 + wm * 32 + mi * 16 + (lane >> 2);
        #pragma unroll
        for (int ni = 0; ni < 8; ni++) {
            int col = n0 + wn * 64 + ni * 8 + (lane & 3) * 2;
            *(float2*)(out + (size_t)row0 * Ntot + col)       = make_float2(d[mi][ni][0], d[mi][ni][1]);
            *(float2*)(out + (size_t)(row0 + 8) * Ntot + col) = make_float2(d[mi][ni][2], d[mi][ni][3]);
        }
    }
}

// ================= 1-pass fp16 B-resident GEMM (V / proj / MLP1) =================
constexpr int BRES   = 128 * 768;             // 98304
constexpr int ASLOT  = 128 * 128;             // 16384
constexpr int GSMEMF = BRES + 3 * ASLOT;      // 147456
constexpr int KST    = 6;                     // K = 384 / 64
constexpr int MCHUNK = 16;

template<int MODE>  // 0: fp32 out = acc   1: fp32 out = acc+bias+res   2: fp16 out = relu(acc+bias)
__global__ void __launch_bounds__(256, 1)
gemm_f16(const __half* __restrict__ A, int Astride,
         const __half* __restrict__ B, int Bstride,
         const float* __restrict__ bias, const float* __restrict__ res,
         void* __restrict__ out, int Ntot) {
    extern __shared__ char smem[];
    const uint32_t sB = smem_u32(smem);
    const uint32_t sA0 = sB + BRES;
    const int tid = threadIdx.x, lane = tid & 31, wid = tid >> 5;
    const int wm = wid >> 1, wn = wid & 1;
    const int n0 = blockIdx.x * 128;

    {
        #pragma unroll 4
        for (int i = 0; i < 24; i++) {
            int cg = i * 256 + tid;
            int row = cg / 48, c = cg - row * 48;
            const __half* src = B + (size_t)(n0 + row) * Bstride + c * 8;
            uint4 v = *(const uint4*)src;
            *(uint4*)(smem + row * 768 + ((c ^ (row & 7)) << 4)) = v;
        }
    }

    const int lrow = tid >> 1, lhalf = tid & 1;
    const uint32_t aswz = (uint32_t)(lrow & 7);

#define LOAD_A(gidx) do { \
        int _mb = (gidx) / KST, _s = (gidx) - _mb * KST; \
        const __half* _src = A + (size_t)((blockIdx.y * MCHUNK + _mb) * 128 + lrow) * Astride \
                           + _s * 64 + lhalf * 32; \
        uint32_t _dst = sA0 + ((gidx) % 3) * ASLOT + (uint32_t)(lrow * 128); \
        CPASYNC16(_dst + (((lhalf * 4 + 0) ^ aswz) << 4), _src); \
        CPASYNC16(_dst + (((lhalf * 4 + 1) ^ aswz) << 4), _src + 8); \
        CPASYNC16(_dst + (((lhalf * 4 + 2) ^ aswz) << 4), _src + 16); \
        CPASYNC16(_dst + (((lhalf * 4 + 3) ^ aswz) << 4), _src + 24); \
    } while (0)

    const int arow0 = wm * 32 + (lane & 15);
    const int achk0 = (lane >> 4);
    const int nl = (lane & 7) + ((lane >> 4) << 3);
    const int kc = (lane >> 3) & 1;
    const int brow0 = wn * 64 + nl;

    LOAD_A(0); CP_COMMIT();
    LOAD_A(1); CP_COMMIT();
    __syncthreads();

    constexpr int G = MCHUNK * KST;
    for (int mb = 0; mb < MCHUNK; mb++) {
        float d[2][8][4];
        #pragma unroll
        for (int i = 0; i < 2; i++)
            #pragma unroll
            for (int j = 0; j < 8; j++)
                #pragma unroll
                for (int q = 0; q < 4; q++) d[i][j][q] = 0.0f;

        for (int s = 0; s < KST; s++) {
            const int g = mb * KST + s;
            CP_WAIT1();
            __syncthreads();
            if (g + 2 < G) LOAD_A(g + 2);
            CP_COMMIT();

            const uint32_t sA = sA0 + (g % 3) * ASLOT;
            #pragma unroll
            for (int kk = 0; kk < 4; kk++) {
                uint32_t a[2][4];
                uint32_t b[4][4];
                #pragma unroll
                for (int mi = 0; mi < 2; mi++) {
                    int row = arow0 + mi * 16;
                    int chunk = kk * 2 + achk0;
                    LDSM4(a[mi], sA + row * 128 + ((chunk ^ (row & 7)) << 4));
                }
                #pragma unroll
                for (int np = 0; np < 4; np++) {
                    int n = brow0 + np * 16;
                    int chunk = s * 8 + kk * 2 + kc;
                    LDSM4(b[np], sB + n * 768 + ((chunk ^ (n & 7)) << 4));
                }
                #pragma unroll
                for (int mi = 0; mi < 2; mi++)
                    #pragma unroll
                    for (int np = 0; np < 4; np++)
                        #pragma unroll
                        for (int sub = 0; sub < 2; sub++)
                            MMA_FP16(d[mi][np * 2 + sub], a[mi], b[np][sub*2], b[np][sub*2+1]);
            }
        }

        const int m0 = (blockIdx.y * MCHUNK + mb) * 128;
        #pragma unroll
        for (int mi = 0; mi < 2; mi++) {
            int row0 = m0 + wm * 32 + mi * 16 + (lane >> 2);
            #pragma unroll
            for (int ni = 0; ni < 8; ni++) {
                int col = n0 + wn * 64 + ni * 8 + (lane & 3) * 2;
                if (MODE == 0) {
                    float* o = (float*)out;
                    *(float2*)(o + (size_t)row0 * Ntot + col)       = make_float2(d[mi][ni][0], d[mi][ni][1]);
                    *(float2*)(o + (size_t)(row0 + 8) * Ntot + col) = make_float2(d[mi][ni][2], d[mi][ni][3]);
                } else if (MODE == 1) {
                    float b0 = bias[col], b1 = bias[col + 1];
                    float* o = (float*)out;
                    float2 r0 = *(const float2*)(res + (size_t)row0 * Ntot + col);
                    float2 r1 = *(const float2*)(res + (size_t)(row0 + 8) * Ntot + col);
                    *(float2*)(o + (size_t)row0 * Ntot + col) =
                        make_float2(d[mi][ni][0] + b0 + r0.x, d[mi][ni][1] + b1 + r0.y);
                    *(float2*)(o + (size_t)(row0 + 8) * Ntot + col) =
                        make_float2(d[mi][ni][2] + b0 + r1.x, d[mi][ni][3] + b1 + r1.y);
                } else {
                    float b0 = bias[col], b1 = bias[col + 1];
                    __half* ob = (__half*)out;
                    *(__half2*)(ob + (size_t)row0 * Ntot + col) =
                        __floats2half2_rn(fmaxf(d[mi][ni][0] + b0, 0.0f), fmaxf(d[mi][ni][1] + b1, 0.0f));
                    *(__half2*)(ob + (size_t)(row0 + 8) * Ntot + col) =
                        __floats2half2_rn(fmaxf(d[mi][ni][2] + b0, 0.0f), fmaxf(d[mi][ni][3] + b1, 0.0f));
                }
            }
        }
    }
#undef LOAD_A
}

// ================= streaming fp16 GEMM (MLP2, K=1536, one launch) =================
constexpr int FPIECE = 128 * 144;       // 18432
constexpr int FSTAGE = 2 * FPIECE;      // 36864
constexpr int GSMEMS = 3 * FSTAGE;      // 110592

__global__ void __launch_bounds__(256)
gemm_f16_stream(const __half* __restrict__ A, const __half* __restrict__ B,
                const float* __restrict__ bias, const float* __restrict__ res,
                float* __restrict__ out, int Kw, int Ntot) {
    extern __shared__ char smem[];
    const uint32_t sbase = smem_u32(smem);
    const int tid = threadIdx.x, lane = tid & 31, wid = tid >> 5;
    const int wm = wid >> 1, wn = wid & 1;
    const int m0 = blockIdx.y * 128, n0 = blockIdx.x * 128;
    const int nstages = Kw >> 6;   // 24

    const int lrow = tid >> 1, lhalf = tid & 1;
    const __half* agp = A + (size_t)(m0 + lrow) * Kw + lhalf * 32;
    const __half* bgp = B + (size_t)(n0 + lrow) * Kw + lhalf * 32;
    const uint32_t ldst = (uint32_t)(lrow * 144 + lhalf * 64);

#define LOAD_STAGE_S(bufi, k0v) do { \
        const uint32_t sb = sbase + (bufi) * FSTAGE; \
        const __half* a0p = agp + (k0v); \
        const __half* b0p = bgp + (k0v); \
        uint32_t d0 = sb + ldst; \
        CPASYNC16(d0 +  0, a0p);      CPASYNC16(d0 + 16, a0p + 8); \
        CPASYNC16(d0 + 32, a0p + 16); CPASYNC16(d0 + 48, a0p + 24); \
        d0 = sb + FPIECE + ldst; \
        CPASYNC16(d0 +  0, b0p);      CPASYNC16(d0 + 16, b0p + 8); \
        CPASYNC16(d0 + 32, b0p + 16); CPASYNC16(d0 + 48, b0p + 24); \
    } while (0)

    float d[2][8][4];
    #pragma unroll
    for (int i = 0; i < 2; i++)
        #pragma unroll
        for (int j = 0; j < 8; j++)
            #pragma unroll
            for (int q = 0; q < 4; q++) d[i][j][q] = 0.0f;

    const uint32_t a_off = (uint32_t)((wm * 32 + (lane & 15)) * 144 + (lane >> 4) * 16);
    const int nl = (lane & 7) + ((lane >> 4) << 3);
    const int kc = (lane >> 3) & 1;
    const uint32_t b_off = (uint32_t)((wn * 64 + nl) * 144 + kc * 16);

    LOAD_STAGE_S(0, 0);  CP_COMMIT();
    LOAD_STAGE_S(1, 64); CP_COMMIT();

    for (int it = 0; it < nstages; it++) {
        CP_WAIT1();
        __syncthreads();
        if (it + 2 < nstages) LOAD_STAGE_S((it + 2) % 3, (it + 2) * 64);
        CP_COMMIT();

        const uint32_t sA = sbase + (it % 3) * FSTAGE;
        const uint32_t sB = sA + FPIECE;
        #pragma unroll
        for (int kk = 0; kk < 4; kk++) {
            uint32_t a[2][4];
            uint32_t b[4][4];
            #pragma unroll
            for (int mi = 0; mi < 2; mi++)
                LDSM4(a[mi], sA + a_off + mi * (16 * 144) + kk * 32);
            #pragma unroll
            for (int np = 0; np < 4; np++)
                LDSM4(b[np], sB + b_off + np * (16 * 144) + kk * 32);
            #pragma unroll
            for (int mi = 0; mi < 2; mi++)
                #pragma unroll
                for (int np = 0; np < 4; np++)
                    #pragma unroll
                    for (int sub = 0; sub < 2; sub++)
                        MMA_FP16(d[mi][np * 2 + sub], a[mi], b[np][sub*2], b[np][sub*2+1]);
        }
    }
#undef LOAD_STAGE_S

    #pragma unroll
    for (int mi = 0; mi < 2; mi++) {
        int row0 = m0 + wm * 32 + mi * 16 + (lane >> 2);
        #pragma unroll
        for (int ni = 0; ni < 8; ni++) {
            int col = n0 + wn * 64 + ni * 8 + (lane & 3) * 2;
            float b0 = bias[col], b1 = bias[col + 1];
            float2 r0 = *(const float2*)(res + (size_t)row0 * Ntot + col);
            float2 r1 = *(const float2*)(res + (size_t)(row0 + 8) * Ntot + col);
            *(float2*)(out + (size_t)row0 * Ntot + col) =
                make_float2(d[mi][ni][0] + b0 + r0.x, d[mi][ni][1] + b1 + r0.y);
            *(float2*)(out + (size_t)(row0 + 8) * Ntot + col) =
                make_float2(d[mi][ni][2] + b0 + r1.x, d[mi][ni][3] + b1 + r1.y);
        }
    }
}

// ---------------- attention (fp32 in, fp16 out) ----------------
__global__ void __launch_bounds__(128)
attn_kernel(const float* __restrict__ qkv, __half* __restrict__ out) {
    const int b = blockIdx.x, h = blockIdx.y;
    const int tid = threadIdx.x;
    const int r = tid >> 1, half = tid & 1;
    __shared__ float ks[SEQ][HSZ];
    __shared__ float vs[SEQ][HSZ];

    for (int i = tid; i < SEQ * (HSZ / 4); i += 128) {
        int s = i / (HSZ / 4), c = i % (HSZ / 4);
        const float* src = qkv + (size_t)(b * SEQ + s) * (3 * EMB) + h * HSZ;
        *(float4*)&ks[s][c * 4] = *(const float4*)(src + EMB + c * 4);
        *(float4*)&vs[s][c * 4] = *(const float4*)(src + 2 * EMB + c * 4);
    }
    float q[24];
    {
        const float* qsrc = qkv + (size_t)(b * SEQ + r) * (3 * EMB) + h * HSZ + half * 24;
        #pragma unroll
        for (int i = 0; i < 6; i++) {
            float4 v = *(const float4*)(qsrc + 4 * i);
            q[4*i] = v.x; q[4*i+1] = v.y; q[4*i+2] = v.z; q[4*i+3] = v.w;
        }
    }
    __syncthreads();

    const uint32_t pmask = 3u << ((tid & 31) & ~1);
    float m = -1e30f, l = 0.0f;
    float o[24];
    #pragma unroll
    for (int dd = 0; dd < 24; dd++) o[dd] = 0.0f;

    for (int s0 = 0; s0 <= r; s0 += 16) {
        float sc[16];
        float bm = -1e30f;
        #pragma unroll
        for (int j = 0; j < 16; j++) {
            int s = s0 + j;
            float pd = 0.0f;
            if (s <= r) {
                const float* kp = &ks[s][half * 24];
                #pragma unroll
                for (int dd = 0; dd < 24; dd++) pd += q[dd] * kp[dd];
            }
            pd += __shfl_xor_sync(pmask, pd, 1);
            sc[j] = (s <= r) ? pd * ATT_SCALE : -1e30f;
            bm = fmaxf(bm, sc[j]);
        }
        float nm = fmaxf(m, bm);
        float alpha = __expf(m - nm);
        l *= alpha;
        #pragma unroll
        for (int dd = 0; dd < 24; dd++) o[dd] *= alpha;
        #pragma unroll
        for (int j = 0; j < 16; j++) {
            float p = __expf(sc[j] - nm);
            l += p;
            int sv = s0 + j; sv = sv < SEQ ? sv : SEQ - 1;
            const float* vp = &vs[sv][half * 24];
            #pragma unroll
            for (int dd = 0; dd < 24; dd++) o[dd] += p * vp[dd];
        }
        m = nm;
    }
    float inv = 1.0f / l;
    __half* op = out + (size_t)(b * SEQ + r) * EMB + h * HSZ + half * 24;
    #pragma unroll
    for (int i = 0; i < 12; i++)
        *(__half2*)(op + 2 * i) = __floats2half2_rn(o[2*i] * inv, o[2*i+1] * inv);
}

// ---------------- launch ----------------
extern "C" void kernel_launch(void* const* d_in, const int* in_sizes, int n_in,
                              void* d_out, int out_size) {
    const float* x     = (const float*)d_in[0];
    const float* ln1_g = (const float*)d_in[1];
    const float* ln1_b = (const float*)d_in[2];
    const float* ln2_g = (const float*)d_in[3];
    const float* ln2_b = (const float*)d_in[4];
    const float* Wq    = (const float*)d_in[5];
    const float* Wk    = (const float*)d_in[6];
    const float* Wv    = (const float*)d_in[7];
    const float* Wp    = (const float*)d_in[8];
    const float* bp    = (const float*)d_in[9];
    const float* W1    = (const float*)d_in[10];
    const float* b1    = (const float*)d_in[11];
    const float* W2    = (const float*)d_in[12];
    const float* b2    = (const float*)d_in[13];
    float* out = (float*)d_out;

    __nv_bfloat16 *ln1, *wqk;
    __half *h1h, *attnh, *h2h, *hidh, *wvh, *wph, *w1h, *w2h;
    float *qkv, *x2;
    cudaGetSymbolAddress((void**)&ln1,   g_ln1);
    cudaGetSymbolAddress((void**)&h1h,   g_h1h);
    cudaGetSymbolAddress((void**)&qkv,   g_qkv);
    cudaGetSymbolAddress((void**)&attnh, g_attnh);
    cudaGetSymbolAddress((void**)&x2,    g_x2);
    cudaGetSymbolAddress((void**)&h2h,   g_h2h);
    cudaGetSymbolAddress((void**)&hidh,  g_hidh);
    cudaGetSymbolAddress((void**)&wqk,   g_wqk);
    cudaGetSymbolAddress((void**)&wvh,   g_wvh);
    cudaGetSymbolAddress((void**)&wph,   g_wph);
    cudaGetSymbolAddress((void**)&w1h,   g_w1h);
    cudaGetSymbolAddress((void**)&w2h,   g_w2h);

    cudaFuncSetAttribute(gemm_bf3,        cudaFuncAttributeMaxDynamicSharedMemorySize, GSMEM3);
    cudaFuncSetAttribute(gemm_f16<0>,     cudaFuncAttributeMaxDynamicSharedMemorySize, GSMEMF);
    cudaFuncSetAttribute(gemm_f16<1>,     cudaFuncAttributeMaxDynamicSharedMemorySize, GSMEMF);
    cudaFuncSetAttribute(gemm_f16<2>,     cudaFuncAttributeMaxDynamicSharedMemorySize, GSMEMF);
    cudaFuncSetAttribute(gemm_f16_stream, cudaFuncAttributeMaxDynamicSharedMemorySize, GSMEMS);

    // weight prep
    prep_wqkv_kernel<<<(NHEAD * EMB * HSZ + 255) / 256, 256>>>(Wq, Wk, Wv);
    prep_w_fp16<<<(EMB * EMB + 255) / 256, 256>>>(Wp, wph, EMB, EMB, EMB);
    prep_w_fp16<<<(EMB * FF + 255) / 256, 256>>>(W1, w1h, EMB, FF, EMB);
    prep_w_fp16<<<(FF * EMB + 255) / 256, 256>>>(W2, w2h, FF, EMB, FF);

    // 1) LN1 -> split bf16 (QK) + fp16 (V)
    ln_fused<0><<<N_TOK / 4, 128>>>(x, ln1_g, ln1_b, ln1, h1h);
    // 2a) QK GEMM (3-pass bf16) -> qkv cols 0..767
    gemm_bf3<<<dim3(6, N_TOK / 128), 256, GSMEM3>>>(ln1, wqk, qkv, EMB, 3 * EMB);
    // 2b) V GEMM (1-pass fp16) -> qkv cols 768..1151
    gemm_f16<0><<<dim3(3, 64), 256, GSMEMF>>>(h1h, EMB, wvh, EMB, nullptr, nullptr,
                                              qkv + 2 * EMB, 3 * EMB);
    // 3) attention -> fp16
    attn_kernel<<<dim3(2048, NHEAD), 128>>>(qkv, attnh);
    // 4) proj + bias + residual(x) -> fp32 x2
    gemm_f16<1><<<dim3(3, 64), 256, GSMEMF>>>(attnh, EMB, wph, EMB, bp, x, x2, EMB);
    // 5) LN2 -> fp16
    ln_fused<1><<<N_TOK / 4, 128>>>(x2, ln2_g, ln2_b, nullptr, h2h);
    // 6) MLP up + relu -> fp16 hidden
    gemm_f16<2><<<dim3(12, 64), 256, GSMEMF>>>(h2h, EMB, w1h, EMB, b1, nullptr, hidh, FF);
    // 7) MLP down (K=1536, one streaming launch) + bias + residual(x2) -> out
    gemm_f16_stream<<<dim3(3, N_TOK / 128), 256, GSMEMS>>>(hidh, w2h, b2, x2, out, FF, EMB);
}

// round 8
// speedup vs baseline: 2.0419x; 1.0181x over previous
#include <cuda_runtime.h>
#include <cuda_bf16.h>
#include <cuda_fp16.h>
#include <cstdint>

// ---------------- problem constants ----------------
constexpr int N_TOK  = 2048 * 64;   // 131072 tokens
constexpr int EMB    = 384;
constexpr int NHEAD  = 8;
constexpr int HSZ    = 48;
constexpr int SEQ    = 64;
constexpr int FF     = 1536;
constexpr float ATT_SCALE = 2.449489742783178f;

// ---------------- scratch (static device memory) ----------------
__device__ __align__(128) __nv_bfloat16 g_ln1 [(size_t)N_TOK * 2 * EMB];    // [hi|lo] for QK
__device__ __align__(128) __half        g_h1h [(size_t)N_TOK * EMB];        // fp16 LN1 (for V)
__device__ __align__(128) float         g_qkv [(size_t)N_TOK * 3 * EMB];    // fp32 q|k|v
__device__ __align__(128) __half        g_attnh[(size_t)N_TOK * EMB];       // fp16
__device__ __align__(128) float         g_x2  [(size_t)N_TOK * EMB];        // fp32 residual
__device__ __align__(128) __half        g_h2h [(size_t)N_TOK * EMB];        // fp16
__device__ __align__(128) __half        g_hidh[(size_t)N_TOK * FF];         // fp16
__device__ __align__(128) __nv_bfloat16 g_wqk [(size_t)(2*EMB) * 2 * EMB];  // [768][hi|lo 768]
__device__ __align__(128) __half        g_wvh [(size_t)EMB * EMB];          // [N][K] fp16
__device__ __align__(128) __half        g_wph [(size_t)EMB * EMB];
__device__ __align__(128) __half        g_w1h [(size_t)FF  * EMB];
__device__ __align__(128) __half        g_w2h [(size_t)EMB * FF];

// ---------------- PTX helpers ----------------
typedef unsigned long long u64;
__device__ __forceinline__ uint32_t smem_u32(const void* p) {
    uint32_t a;
    asm("{ .reg .u64 t; cvta.to.shared.u64 t, %1; cvt.u32.u64 %0, t; }" : "=r"(a) : "l"(p));
    return a;
}
#define CPASYNC16(dst, src) asm volatile("cp.async.cg.shared.global [%0], [%1], 16;" :: "r"(dst), "l"(src) : "memory")
#define CP_COMMIT()         asm volatile("cp.async.commit_group;" ::: "memory")
#define CP_WAIT1()          asm volatile("cp.async.wait_group 1;" ::: "memory")

#define LDSM4(r, addr) \
    asm volatile("ldmatrix.sync.aligned.m8n8.x4.shared.b16 {%0,%1,%2,%3}, [%4];" \
        : "=r"((r)[0]), "=r"((r)[1]), "=r"((r)[2]), "=r"((r)[3]) : "r"(addr))

#define MMA_BF16(d, a, b0, b1) \
    asm volatile("mma.sync.aligned.m16n8k16.row.col.f32.bf16.bf16.f32 " \
        "{%0,%1,%2,%3}, {%4,%5,%6,%7}, {%8,%9}, {%0,%1,%2,%3};" \
        : "+f"((d)[0]), "+f"((d)[1]), "+f"((d)[2]), "+f"((d)[3]) \
        : "r"((a)[0]), "r"((a)[1]), "r"((a)[2]), "r"((a)[3]), "r"(b0), "r"(b1))

#define MMA_FP16(d, a, b0, b1) \
    asm volatile("mma.sync.aligned.m16n8k16.row.col.f32.f16.f16.f32 " \
        "{%0,%1,%2,%3}, {%4,%5,%6,%7}, {%8,%9}, {%0,%1,%2,%3};" \
        : "+f"((d)[0]), "+f"((d)[1]), "+f"((d)[2]), "+f"((d)[3]) \
        : "r"((a)[0]), "r"((a)[1]), "r"((a)[2]), "r"((a)[3]), "r"(b0), "r"(b1))

__device__ __forceinline__ u64 pk2(float lo, float hi) {
    u64 r; asm("mov.b64 %0, {%1, %2};" : "=l"(r) : "f"(lo), "f"(hi)); return r;
}
__device__ __forceinline__ float2 upk2(u64 p) {
    float2 r; asm("mov.b64 {%0, %1}, %2;" : "=f"(r.x), "=f"(r.y) : "l"(p)); return r;
}
#define FMA2(d, a, b) asm("fma.rn.f32x2 %0, %1, %2, %0;" : "+l"(d) : "l"(a), "l"(b))
#define MUL2(d, a, b) asm("mul.rn.f32x2 %0, %1, %2;" : "=l"(d) : "l"(a), "l"(b))

__device__ __forceinline__ __nv_bfloat16 bf_hi(float v) { return __float2bfloat16(v); }
__device__ __forceinline__ __nv_bfloat16 bf_lo(float v, __nv_bfloat16 hi) {
    return __float2bfloat16(v - __bfloat162float(hi));
}

// ---------------- stage 1: LN1 (+split outputs) fused with ALL weight prep ----------------
constexpr int LN_BLOCKS   = N_TOK / 4;               // 32768
constexpr int PREP_TOTAL  = 147456 + 147456 + 589824 + 589824;  // 1474560
constexpr int PREP_BLOCKS = PREP_TOTAL / 512;        // 2880 (128 thr x 4 elems)

__global__ void __launch_bounds__(128)
stage1_kernel(const float* __restrict__ in, const float* __restrict__ g,
              const float* __restrict__ b, __nv_bfloat16* __restrict__ bfout,
              __half* __restrict__ hout,
              const float* __restrict__ Wq, const float* __restrict__ Wk,
              const float* __restrict__ Wv, const float* __restrict__ Wp,
              const float* __restrict__ W1, const float* __restrict__ W2) {
    if (blockIdx.x < LN_BLOCKS) {
        const int row = blockIdx.x * 4 + (threadIdx.x >> 5);
        const int lane = threadIdx.x & 31;
        const float* rp = in + (size_t)row * EMB + lane * 12;
        float4 v0 = *(const float4*)(rp), v1 = *(const float4*)(rp + 4), v2 = *(const float4*)(rp + 8);
        float vv[12] = {v0.x, v0.y, v0.z, v0.w, v1.x, v1.y, v1.z, v1.w, v2.x, v2.y, v2.z, v2.w};
        float s = 0.0f, ss = 0.0f;
        #pragma unroll
        for (int i = 0; i < 12; i++) { s += vv[i]; ss += vv[i] * vv[i]; }
        #pragma unroll
        for (int off = 16; off > 0; off >>= 1) {
            s  += __shfl_xor_sync(0xffffffffu, s, off);
            ss += __shfl_xor_sync(0xffffffffu, ss, off);
        }
        float mu = s * (1.0f / EMB);
        float var = ss * (1.0f / EMB) - mu * mu;
        float rs = rsqrtf(var + 1e-5f);
        const float* gp = g + lane * 12;
        const float* bp = b + lane * 12;
        float o[12];
        #pragma unroll
        for (int i = 0; i < 12; i++) o[i] = (vv[i] - mu) * rs * gp[i] + bp[i];
        __half hh[12];
        #pragma unroll
        for (int i = 0; i < 12; i++) hh[i] = __float2half(o[i]);
        __half* hrow = hout + (size_t)row * EMB + lane * 12;
        *(uint2*)(hrow)     = *(uint2*)(hh);
        *(uint2*)(hrow + 4) = *(uint2*)(hh + 4);
        *(uint2*)(hrow + 8) = *(uint2*)(hh + 8);
        __nv_bfloat16 hi[12], lo[12];
        #pragma unroll
        for (int i = 0; i < 12; i++) { hi[i] = bf_hi(o[i]); lo[i] = bf_lo(o[i], hi[i]); }
        __nv_bfloat16* orow = bfout + (size_t)row * 2 * EMB + lane * 12;
        *(uint2*)(orow)     = *(uint2*)(hi);
        *(uint2*)(orow + 4) = *(uint2*)(hi + 4);
        *(uint2*)(orow + 8) = *(uint2*)(hi + 8);
        __nv_bfloat16* lrow = orow + EMB;
        *(uint2*)(lrow)     = *(uint2*)(lo);
        *(uint2*)(lrow + 4) = *(uint2*)(lo + 4);
        *(uint2*)(lrow + 8) = *(uint2*)(lo + 8);
    } else {
        // weight prep, 4 elements per thread
        int base = (blockIdx.x - LN_BLOCKS) * 512 + threadIdx.x * 4;
        #pragma unroll
        for (int e = 0; e < 4; e++) {
            int i = base + e;
            if (i < 147456) {                 // Wq/Wk -> g_wqk split, Wv -> g_wvh
                int h = i / (EMB * HSZ), r = i % (EMB * HSZ), c = r / HSZ, d = r % HSZ;
                int n = h * HSZ + d;
                float q = Wq[i], k = Wk[i];
                __nv_bfloat16 qh = bf_hi(q), kh = bf_hi(k);
                size_t rq = (size_t)n * 2 * EMB, rk = (size_t)(EMB + n) * 2 * EMB;
                g_wqk[rq + c] = qh;  g_wqk[rq + EMB + c] = bf_lo(q, qh);
                g_wqk[rk + c] = kh;  g_wqk[rk + EMB + c] = bf_lo(k, kh);
                g_wvh[(size_t)n * EMB + c] = __float2half(Wv[i]);
            } else if (i < 294912) {          // Wp [384x384]
                int j = i - 147456;
                int k = j / EMB, n = j % EMB;
                g_wph[(size_t)n * EMB + k] = __float2half(Wp[j]);
            } else if (i < 884736) {          // W1 [384x1536]
                int j = i - 294912;
                int k = j / FF, n = j % FF;
                g_w1h[(size_t)n * EMB + k] = __float2half(W1[j]);
            } else {                          // W2 [1536x384]
                int j = i - 884736;
                int k = j / EMB, n = j % EMB;
                g_w2h[(size_t)n * FF + k] = __float2half(W2[j]);
            }
        }
    }
}

// ---------------- LN2 (fp16 out only) ----------------
__global__ void __launch_bounds__(128)
ln2_kernel(const float* __restrict__ in, const float* __restrict__ g,
           const float* __restrict__ b, __half* __restrict__ hout) {
    const int row = blockIdx.x * 4 + (threadIdx.x >> 5);
    const int lane = threadIdx.x & 31;
    const float* rp = in + (size_t)row * EMB + lane * 12;
    float4 v0 = *(const float4*)(rp), v1 = *(const float4*)(rp + 4), v2 = *(const float4*)(rp + 8);
    float vv[12] = {v0.x, v0.y, v0.z, v0.w, v1.x, v1.y, v1.z, v1.w, v2.x, v2.y, v2.z, v2.w};
    float s = 0.0f, ss = 0.0f;
    #pragma unroll
    for (int i = 0; i < 12; i++) { s += vv[i]; ss += vv[i] * vv[i]; }
    #pragma unroll
    for (int off = 16; off > 0; off >>= 1) {
        s  += __shfl_xor_sync(0xffffffffu, s, off);
        ss += __shfl_xor_sync(0xffffffffu, ss, off);
    }
    float mu = s * (1.0f / EMB);
    float var = ss * (1.0f / EMB) - mu * mu;
    float rs = rsqrtf(var + 1e-5f);
    const float* gp = g + lane * 12;
    const float* bp = b + lane * 12;
    __half hh[12];
    #pragma unroll
    for (int i = 0; i < 12; i++) hh[i] = __float2half((vv[i] - mu) * rs * gp[i] + bp[i]);
    __half* hrow = hout + (size_t)row * EMB + lane * 12;
    *(uint2*)(hrow)     = *(uint2*)(hh);
    *(uint2*)(hrow + 4) = *(uint2*)(hh + 4);
    *(uint2*)(hrow + 8) = *(uint2*)(hh + 8);
}

// ================= fat QKV kernel: x<6 -> QK (3-pass bf16), x>=6 -> V (1-pass fp16) =================
constexpr int PIECE  = 128 * 144;
constexpr int STAGE3 = 4 * PIECE;
constexpr int GSMEM3 = 3 * STAGE3;       // 221184
constexpr int FPIECE = 128 * 144;
constexpr int FSTAGE = 2 * FPIECE;       // 36864

__global__ void __launch_bounds__(256, 1)
gemm_qkv(const __nv_bfloat16* __restrict__ Aqk, const __nv_bfloat16* __restrict__ Bqk,
         const __half* __restrict__ Av, const __half* __restrict__ Bv,
         float* __restrict__ out) {
    extern __shared__ char smem[];
    const uint32_t sbase = smem_u32(smem);
    const int tid = threadIdx.x, lane = tid & 31, wid = tid >> 5;
    const int wm = wid >> 1, wn = wid & 1;
    const int m0 = blockIdx.y * 128;
    const int lrow = tid >> 1, lhalf = tid & 1;
    const uint32_t ldst = (uint32_t)(lrow * 144 + lhalf * 64);
    const uint32_t a_off = (uint32_t)((wm * 32 + (lane & 15)) * 144 + (lane >> 4) * 16);
    const int nl = (lane & 7) + ((lane >> 4) << 3);
    const int kc = (lane >> 3) & 1;
    const uint32_t b_off = (uint32_t)((wn * 64 + nl) * 144 + kc * 16);

    float d[2][8][4];
    #pragma unroll
    for (int i = 0; i < 2; i++)
        #pragma unroll
        for (int j = 0; j < 8; j++)
            #pragma unroll
            for (int q = 0; q < 4; q++) d[i][j][q] = 0.0f;

    if (blockIdx.x < 6) {
        // ---------- QK path: 3-pass bf16, K=384 ----------
        const int n0 = blockIdx.x * 128;
        const __nv_bfloat16* agp = Aqk + (size_t)(m0 + lrow) * (2 * EMB) + lhalf * 32;
        const __nv_bfloat16* bgp = Bqk + (size_t)(n0 + lrow) * (2 * EMB) + lhalf * 32;

#define LOAD_STAGE3(bufi, k0v) do { \
        const uint32_t sb = sbase + (bufi) * STAGE3; \
        const __nv_bfloat16* a0p = agp + (k0v); \
        const __nv_bfloat16* b0p = bgp + (k0v); \
        uint32_t d0 = sb + ldst; \
        CPASYNC16(d0 +  0, a0p);      CPASYNC16(d0 + 16, a0p + 8); \
        CPASYNC16(d0 + 32, a0p + 16); CPASYNC16(d0 + 48, a0p + 24); \
        d0 += PIECE; a0p += EMB; \
        CPASYNC16(d0 +  0, a0p);      CPASYNC16(d0 + 16, a0p + 8); \
        CPASYNC16(d0 + 32, a0p + 16); CPASYNC16(d0 + 48, a0p + 24); \
        d0 = sb + 2 * PIECE + ldst; \
        CPASYNC16(d0 +  0, b0p);      CPASYNC16(d0 + 16, b0p + 8); \
        CPASYNC16(d0 + 32, b0p + 16); CPASYNC16(d0 + 48, b0p + 24); \
        d0 += PIECE; b0p += EMB; \
        CPASYNC16(d0 +  0, b0p);      CPASYNC16(d0 + 16, b0p + 8); \
        CPASYNC16(d0 + 32, b0p + 16); CPASYNC16(d0 + 48, b0p + 24); \
    } while (0)

        LOAD_STAGE3(0, 0);  CP_COMMIT();
        LOAD_STAGE3(1, 64); CP_COMMIT();

        #pragma unroll 1
        for (int it = 0; it < 6; it++) {
            CP_WAIT1();
            __syncthreads();
            if (it + 2 < 6) LOAD_STAGE3((it + 2) % 3, (it + 2) * 64);
            CP_COMMIT();

            const uint32_t sA = sbase + (it % 3) * STAGE3;
            const uint32_t sB = sA + 2 * PIECE;
            #pragma unroll
            for (int kk = 0; kk < 4; kk++) {
                uint32_t a[2][2][4];
                uint32_t b[2][4][4];
                #pragma unroll
                for (int sp = 0; sp < 2; sp++)
                    #pragma unroll
                    for (int mi = 0; mi < 2; mi++)
                        LDSM4(a[sp][mi], sA + sp * PIECE + a_off + mi * (16 * 144) + kk * 32);
                #pragma unroll
                for (int sp = 0; sp < 2; sp++)
                    #pragma unroll
                    for (int np = 0; np < 4; np++)
                        LDSM4(b[sp][np], sB + sp * PIECE + b_off + np * (16 * 144) + kk * 32);
                #pragma unroll
                for (int mi = 0; mi < 2; mi++)
                    #pragma unroll
                    for (int np = 0; np < 4; np++)
                        #pragma unroll
                        for (int sub = 0; sub < 2; sub++)
                            MMA_BF16(d[mi][np * 2 + sub], a[0][mi], b[0][np][sub*2], b[0][np][sub*2+1]);
                #pragma unroll
                for (int mi = 0; mi < 2; mi++)
                    #pragma unroll
                    for (int np = 0; np < 4; np++)
                        #pragma unroll
                        for (int sub = 0; sub < 2; sub++)
                            MMA_BF16(d[mi][np * 2 + sub], a[0][mi], b[1][np][sub*2], b[1][np][sub*2+1]);
                #pragma unroll
                for (int mi = 0; mi < 2; mi++)
                    #pragma unroll
                    for (int np = 0; np < 4; np++)
                        #pragma unroll
                        for (int sub = 0; sub < 2; sub++)
                            MMA_BF16(d[mi][np * 2 + sub], a[1][mi], b[0][np][sub*2], b[0][np][sub*2+1]);
            }
        }
#undef LOAD_STAGE3

        #pragma unroll
        for (int mi = 0; mi < 2; mi++) {
            int row0 = m0 + wm * 32 + mi * 16 + (lane >> 2);
            #pragma unroll
            for (int ni = 0; ni < 8; ni++) {
                int col = n0 + wn * 64 + ni * 8 + (lane & 3) * 2;
                *(float2*)(out + (size_t)row0 * (3 * EMB) + col)       = make_float2(d[mi][ni][0], d[mi][ni][1]);
                *(float2*)(out + (size_t)(row0 + 8) * (3 * EMB) + col) = make_float2(d[mi][ni][2], d[mi][ni][3]);
            }
        }
    } else {
        // ---------- V path: 1-pass fp16 streaming, K=384 ----------
        const int n0 = (blockIdx.x - 6) * 128;
        const __half* agp = Av + (size_t)(m0 + lrow) * EMB + lhalf * 32;
        const __half* bgp = Bv + (size_t)(n0 + lrow) * EMB + lhalf * 32;

#define LOAD_STAGE_V(bufi, k0v) do { \
        const uint32_t sb = sbase + (bufi) * FSTAGE; \
        const __half* a0p = agp + (k0v); \
        const __half* b0p = bgp + (k0v); \
        uint32_t d0 = sb + ldst; \
        CPASYNC16(d0 +  0, a0p);      CPASYNC16(d0 + 16, a0p + 8); \
        CPASYNC16(d0 + 32, a0p + 16); CPASYNC16(d0 + 48, a0p + 24); \
        d0 = sb + FPIECE + ldst; \
        CPASYNC16(d0 +  0, b0p);      CPASYNC16(d0 + 16, b0p + 8); \
        CPASYNC16(d0 + 32, b0p + 16); CPASYNC16(d0 + 48, b0p + 24); \
    } while (0)

        LOAD_STAGE_V(0, 0);  CP_COMMIT();
        LOAD_STAGE_V(1, 64); CP_COMMIT();

        #pragma unroll 1
        for (int it = 0; it < 6; it++) {
            CP_WAIT1();
            __syncthreads();
            if (it + 2 < 6) LOAD_STAGE_V((it + 2) % 3, (it + 2) * 64);
            CP_COMMIT();

            const uint32_t sA = sbase + (it % 3) * FSTAGE;
            const uint32_t sB = sA + FPIECE;
            #pragma unroll
            for (int kk = 0; kk < 4; kk++) {
                uint32_t a[2][4];
                uint32_t b[4][4];
                #pragma unroll
                for (int mi = 0; mi < 2; mi++)
                    LDSM4(a[mi], sA + a_off + mi * (16 * 144) + kk * 32);
                #pragma unroll
                for (int np = 0; np < 4; np++)
                    LDSM4(b[np], sB + b_off + np * (16 * 144) + kk * 32);
                #pragma unroll
                for (int mi = 0; mi < 2; mi++)
                    #pragma unroll
                    for (int np = 0; np < 4; np++)
                        #pragma unroll
                        for (int sub = 0; sub < 2; sub++)
                            MMA_FP16(d[mi][np * 2 + sub], a[mi], b[np][sub*2], b[np][sub*2+1]);
            }
        }
#undef LOAD_STAGE_V

        #pragma unroll
        for (int mi = 0; mi < 2; mi++) {
            int row0 = m0 + wm * 32 + mi * 16 + (lane >> 2);
            #pragma unroll
            for (int ni = 0; ni < 8; ni++) {
                int col = 2 * EMB + n0 + wn * 64 + ni * 8 + (lane & 3) * 2;
                *(float2*)(out + (size_t)row0 * (3 * EMB) + col)       = make_float2(d[mi][ni][0], d[mi][ni][1]);
                *(float2*)(out + (size_t)(row0 + 8) * (3 * EMB) + col) = make_float2(d[mi][ni][2], d[mi][ni][3]);
            }
        }
    }
}

// ================= 1-pass fp16 B-resident GEMM (proj / MLP1) =================
constexpr int BRES   = 128 * 768;
constexpr int ASLOT  = 128 * 128;
constexpr int GSMEMF = BRES + 3 * ASLOT;      // 147456
constexpr int KST    = 6;
constexpr int MCHUNK = 16;

template<int MODE>  // 1: fp32 out = acc+bias+res   2: fp16 out = relu(acc+bias)
__global__ void __launch_bounds__(256, 1)
gemm_f16(const __half* __restrict__ A, int Astride,
         const __half* __restrict__ B, int Bstride,
         const float* __restrict__ bias, const float* __restrict__ res,
         void* __restrict__ out, int Ntot) {
    extern __shared__ char smem[];
    const uint32_t sB = smem_u32(smem);
    const uint32_t sA0 = sB + BRES;
    const int tid = threadIdx.x, lane = tid & 31, wid = tid >> 5;
    const int wm = wid >> 1, wn = wid & 1;
    const int n0 = blockIdx.x * 128;

    {
        #pragma unroll 4
        for (int i = 0; i < 24; i++) {
            int cg = i * 256 + tid;
            int row = cg / 48, c = cg - row * 48;
            const __half* src = B + (size_t)(n0 + row) * Bstride + c * 8;
            uint4 v = *(const uint4*)src;
            *(uint4*)(smem + row * 768 + ((c ^ (row & 7)) << 4)) = v;
        }
    }

    const int lrow = tid >> 1, lhalf = tid & 1;
    const uint32_t aswz = (uint32_t)(lrow & 7);

#define LOAD_A(gidx) do { \
        int _mb = (gidx) / KST, _s = (gidx) - _mb * KST; \
        const __half* _src = A + (size_t)((blockIdx.y * MCHUNK + _mb) * 128 + lrow) * Astride \
                           + _s * 64 + lhalf * 32; \
        uint32_t _dst = sA0 + ((gidx) % 3) * ASLOT + (uint32_t)(lrow * 128); \
        CPASYNC16(_dst + (((lhalf * 4 + 0) ^ aswz) << 4), _src); \
        CPASYNC16(_dst + (((lhalf * 4 + 1) ^ aswz) << 4), _src + 8); \
        CPASYNC16(_dst + (((lhalf * 4 + 2) ^ aswz) << 4), _src + 16); \
        CPASYNC16(_dst + (((lhalf * 4 + 3) ^ aswz) << 4), _src + 24); \
    } while (0)

    const int arow0 = wm * 32 + (lane & 15);
    const int achk0 = (lane >> 4);
    const int nl = (lane & 7) + ((lane >> 4) << 3);
    const int kc = (lane >> 3) & 1;
    const int brow0 = wn * 64 + nl;

    LOAD_A(0); CP_COMMIT();
    LOAD_A(1); CP_COMMIT();
    __syncthreads();

    constexpr int G = MCHUNK * KST;
    for (int mb = 0; mb < MCHUNK; mb++) {
        float d[2][8][4];
        #pragma unroll
        for (int i = 0; i < 2; i++)
            #pragma unroll
            for (int j = 0; j < 8; j++)
                #pragma unroll
                for (int q = 0; q < 4; q++) d[i][j][q] = 0.0f;

        for (int s = 0; s < KST; s++) {
            const int g = mb * KST + s;
            CP_WAIT1();
            __syncthreads();
            if (g + 2 < G) LOAD_A(g + 2);
            CP_COMMIT();

            const uint32_t sA = sA0 + (g % 3) * ASLOT;
            #pragma unroll
            for (int kk = 0; kk < 4; kk++) {
                uint32_t a[2][4];
                uint32_t b[4][4];
                #pragma unroll
                for (int mi = 0; mi < 2; mi++) {
                    int row = arow0 + mi * 16;
                    int chunk = kk * 2 + achk0;
                    LDSM4(a[mi], sA + row * 128 + ((chunk ^ (row & 7)) << 4));
                }
                #pragma unroll
                for (int np = 0; np < 4; np++) {
                    int n = brow0 + np * 16;
                    int chunk = s * 8 + kk * 2 + kc;
                    LDSM4(b[np], sB + n * 768 + ((chunk ^ (n & 7)) << 4));
                }
                #pragma unroll
                for (int mi = 0; mi < 2; mi++)
                    #pragma unroll
                    for (int np = 0; np < 4; np++)
                        #pragma unroll
                        for (int sub = 0; sub < 2; sub++)
                            MMA_FP16(d[mi][np * 2 + sub], a[mi], b[np][sub*2], b[np][sub*2+1]);
            }
        }

        const int m0 = (blockIdx.y * MCHUNK + mb) * 128;
        #pragma unroll
        for (int mi = 0; mi < 2; mi++) {
            int row0 = m0 + wm * 32 + mi * 16 + (lane >> 2);
            #pragma unroll
            for (int ni = 0; ni < 8; ni++) {
                int col = n0 + wn * 64 + ni * 8 + (lane & 3) * 2;
                if (MODE == 1) {
                    float b0 = bias[col], b1 = bias[col + 1];
                    float* o = (float*)out;
                    float2 r0 = *(const float2*)(res + (size_t)row0 * Ntot + col);
                    float2 r1 = *(const float2*)(res + (size_t)(row0 + 8) * Ntot + col);
                    *(float2*)(o + (size_t)row0 * Ntot + col) =
                        make_float2(d[mi][ni][0] + b0 + r0.x, d[mi][ni][1] + b1 + r0.y);
                    *(float2*)(o + (size_t)(row0 + 8) * Ntot + col) =
                        make_float2(d[mi][ni][2] + b0 + r1.x, d[mi][ni][3] + b1 + r1.y);
                } else {
                    float b0 = bias[col], b1 = bias[col + 1];
                    __half* ob = (__half*)out;
                    *(__half2*)(ob + (size_t)row0 * Ntot + col) =
                        __floats2half2_rn(fmaxf(d[mi][ni][0] + b0, 0.0f), fmaxf(d[mi][ni][1] + b1, 0.0f));
                    *(__half2*)(ob + (size_t)(row0 + 8) * Ntot + col) =
                        __floats2half2_rn(fmaxf(d[mi][ni][2] + b0, 0.0f), fmaxf(d[mi][ni][3] + b1, 0.0f));
                }
            }
        }
    }
#undef LOAD_A
}

// ================= streaming fp16 GEMM (MLP2, K=1536) =================
constexpr int GSMEMS = 3 * FSTAGE;      // 110592

__global__ void __launch_bounds__(256)
gemm_f16_stream(const __half* __restrict__ A, const __half* __restrict__ B,
                const float* __restrict__ bias, const float* __restrict__ res,
                float* __restrict__ out, int Kw, int Ntot) {
    extern __shared__ char smem[];
    const uint32_t sbase = smem_u32(smem);
    const int tid = threadIdx.x, lane = tid & 31, wid = tid >> 5;
    const int wm = wid >> 1, wn = wid & 1;
    const int m0 = blockIdx.y * 128, n0 = blockIdx.x * 128;
    const int nstages = Kw >> 6;

    const int lrow = tid >> 1, lhalf = tid & 1;
    const __half* agp = A + (size_t)(m0 + lrow) * Kw + lhalf * 32;
    const __half* bgp = B + (size_t)(n0 + lrow) * Kw + lhalf * 32;
    const uint32_t ldst = (uint32_t)(lrow * 144 + lhalf * 64);

#define LOAD_STAGE_S(bufi, k0v) do { \
        const uint32_t sb = sbase + (bufi) * FSTAGE; \
        const __half* a0p = agp + (k0v); \
        const __half* b0p = bgp + (k0v); \
        uint32_t d0 = sb + ldst; \
        CPASYNC16(d0 +  0, a0p);      CPASYNC16(d0 + 16, a0p + 8); \
        CPASYNC16(d0 + 32, a0p + 16); CPASYNC16(d0 + 48, a0p + 24); \
        d0 = sb + FPIECE + ldst; \
        CPASYNC16(d0 +  0, b0p);      CPASYNC16(d0 + 16, b0p + 8); \
        CPASYNC16(d0 + 32, b0p + 16); CPASYNC16(d0 + 48, b0p + 24); \
    } while (0)

    float d[2][8][4];
    #pragma unroll
    for (int i = 0; i < 2; i++)
        #pragma unroll
        for (int j = 0; j < 8; j++)
            #pragma unroll
            for (int q = 0; q < 4; q++) d[i][j][q] = 0.0f;

    const uint32_t a_off = (uint32_t)((wm * 32 + (lane & 15)) * 144 + (lane >> 4) * 16);
    const int nl = (lane & 7) + ((lane >> 4) << 3);
    const int kc = (lane >> 3) & 1;
    const uint32_t b_off = (uint32_t)((wn * 64 + nl) * 144 + kc * 16);

    LOAD_STAGE_S(0, 0);  CP_COMMIT();
    LOAD_STAGE_S(1, 64); CP_COMMIT();

    for (int it = 0; it < nstages; it++) {
        CP_WAIT1();
        __syncthreads();
        if (it + 2 < nstages) LOAD_STAGE_S((it + 2) % 3, (it + 2) * 64);
        CP_COMMIT();

        const uint32_t sA = sbase + (it % 3) * FSTAGE;
        const uint32_t sB = sA + FPIECE;
        #pragma unroll
        for (int kk = 0; kk < 4; kk++) {
            uint32_t a[2][4];
            uint32_t b[4][4];
            #pragma unroll
            for (int mi = 0; mi < 2; mi++)
                LDSM4(a[mi], sA + a_off + mi * (16 * 144) + kk * 32);
            #pragma unroll
            for (int np = 0; np < 4; np++)
                LDSM4(b[np], sB + b_off + np * (16 * 144) + kk * 32);
            #pragma unroll
            for (int mi = 0; mi < 2; mi++)
                #pragma unroll
                for (int np = 0; np < 4; np++)
                    #pragma unroll
                    for (int sub = 0; sub < 2; sub++)
                        MMA_FP16(d[mi][np * 2 + sub], a[mi], b[np][sub*2], b[np][sub*2+1]);
        }
    }
#undef LOAD_STAGE_S

    #pragma unroll
    for (int mi = 0; mi < 2; mi++) {
        int row0 = m0 + wm * 32 + mi * 16 + (lane >> 2);
        #pragma unroll
        for (int ni = 0; ni < 8; ni++) {
            int col = n0 + wn * 64 + ni * 8 + (lane & 3) * 2;
            float b0 = bias[col], b1 = bias[col + 1];
            float2 r0 = *(const float2*)(res + (size_t)row0 * Ntot + col);
            float2 r1 = *(const float2*)(res + (size_t)(row0 + 8) * Ntot + col);
            *(float2*)(out + (size_t)row0 * Ntot + col) =
                make_float2(d[mi][ni][0] + b0 + r0.x, d[mi][ni][1] + b1 + r0.y);
            *(float2*)(out + (size_t)(row0 + 8) * Ntot + col) =
                make_float2(d[mi][ni][2] + b0 + r1.x, d[mi][ni][3] + b1 + r1.y);
        }
    }
}

// ---------------- attention (fp32 in, fp16 out) with f32x2 packed math ----------------
__global__ void __launch_bounds__(128)
attn_kernel(const float* __restrict__ qkv, __half* __restrict__ out) {
    const int b = blockIdx.x, h = blockIdx.y;
    const int tid = threadIdx.x;
    const int r = tid >> 1, half = tid & 1;
    __shared__ float ks[SEQ][HSZ];
    __shared__ float vs[SEQ][HSZ];

    for (int i = tid; i < SEQ * (HSZ / 4); i += 128) {
        int s = i / (HSZ / 4), c = i % (HSZ / 4);
        const float* src = qkv + (size_t)(b * SEQ + s) * (3 * EMB) + h * HSZ;
        *(float4*)&ks[s][c * 4] = *(const float4*)(src + EMB + c * 4);
        *(float4*)&vs[s][c * 4] = *(const float4*)(src + 2 * EMB + c * 4);
    }
    u64 q2[12];
    {
        const float* qsrc = qkv + (size_t)(b * SEQ + r) * (3 * EMB) + h * HSZ + half * 24;
        #pragma unroll
        for (int i = 0; i < 6; i++) {
            float4 v = *(const float4*)(qsrc + 4 * i);
            q2[2 * i]     = pk2(v.x, v.y);
            q2[2 * i + 1] = pk2(v.z, v.w);
        }
    }
    __syncthreads();

    const uint32_t pmask = 3u << ((tid & 31) & ~1);
    float m = -1e30f, l = 0.0f;
    u64 o2[12];
    #pragma unroll
    for (int i = 0; i < 12; i++) o2[i] = 0ull;

    for (int s0 = 0; s0 <= r; s0 += 16) {
        float sc[16];
        float bm = -1e30f;
        #pragma unroll
        for (int j = 0; j < 16; j++) {
            int s = s0 + j;
            float pd = 0.0f;
            if (s <= r) {
                const u64* kp2 = (const u64*)&ks[s][half * 24];
                u64 acc = 0ull;
                #pragma unroll
                for (int i = 0; i < 12; i++) FMA2(acc, q2[i], kp2[i]);
                float2 ac = upk2(acc);
                pd = ac.x + ac.y;
            }
            pd += __shfl_xor_sync(pmask, pd, 1);
            sc[j] = (s <= r) ? pd * ATT_SCALE : -1e30f;
            bm = fmaxf(bm, sc[j]);
        }
        float nm = fmaxf(m, bm);
        float alpha = __expf(m - nm);
        l *= alpha;
        u64 a2 = pk2(alpha, alpha);
        #pragma unroll
        for (int i = 0; i < 12; i++) { u64 t; MUL2(t, o2[i], a2); o2[i] = t; }
        #pragma unroll
        for (int j = 0; j < 16; j++) {
            float p = __expf(sc[j] - nm);
            l += p;
            int sv = s0 + j; sv = sv < SEQ ? sv : SEQ - 1;
            const u64* vp2 = (const u64*)&vs[sv][half * 24];
            u64 p2v = pk2(p, p);
            #pragma unroll
            for (int i = 0; i < 12; i++) FMA2(o2[i], p2v, vp2[i]);
        }
        m = nm;
    }
    float inv = 1.0f / l;
    __half* op = out + (size_t)(b * SEQ + r) * EMB + h * HSZ + half * 24;
    #pragma unroll
    for (int i = 0; i < 12; i++) {
        float2 f = upk2(o2[i]);
        *(__half2*)(op + 2 * i) = __floats2half2_rn(f.x * inv, f.y * inv);
    }
}

// ---------------- launch ----------------
extern "C" void kernel_launch(void* const* d_in, const int* in_sizes, int n_in,
                              void* d_out, int out_size) {
    const float* x     = (const float*)d_in[0];
    const float* ln1_g = (const float*)d_in[1];
    const float* ln1_b = (const float*)d_in[2];
    const float* ln2_g = (const float*)d_in[3];
    const float* ln2_b = (const float*)d_in[4];
    const float* Wq    = (const float*)d_in[5];
    const float* Wk    = (const float*)d_in[6];
    const float* Wv    = (const float*)d_in[7];
    const float* Wp    = (const float*)d_in[8];
    const float* bp    = (const float*)d_in[9];
    const float* W1    = (const float*)d_in[10];
    const float* b1    = (const float*)d_in[11];
    const float* W2    = (const float*)d_in[12];
    const float* b2    = (const float*)d_in[13];
    float* out = (float*)d_out;

    __nv_bfloat16 *ln1, *wqk;
    __half *h1h, *attnh, *h2h, *hidh, *wvh, *wph, *w1h, *w2h;
    float *qkv, *x2;
    cudaGetSymbolAddress((void**)&ln1,   g_ln1);
    cudaGetSymbolAddress((void**)&h1h,   g_h1h);
    cudaGetSymbolAddress((void**)&qkv,   g_qkv);
    cudaGetSymbolAddress((void**)&attnh, g_attnh);
    cudaGetSymbolAddress((void**)&x2,    g_x2);
    cudaGetSymbolAddress((void**)&h2h,   g_h2h);
    cudaGetSymbolAddress((void**)&hidh,  g_hidh);
    cudaGetSymbolAddress((void**)&wqk,   g_wqk);
    cudaGetSymbolAddress((void**)&wvh,   g_wvh);
    cudaGetSymbolAddress((void**)&wph,   g_wph);
    cudaGetSymbolAddress((void**)&w1h,   g_w1h);
    cudaGetSymbolAddress((void**)&w2h,   g_w2h);

    cudaFuncSetAttribute(gemm_qkv,        cudaFuncAttributeMaxDynamicSharedMemorySize, GSMEM3);
    cudaFuncSetAttribute(gemm_f16<1>,     cudaFuncAttributeMaxDynamicSharedMemorySize, GSMEMF);
    cudaFuncSetAttribute(gemm_f16<2>,     cudaFuncAttributeMaxDynamicSharedMemorySize, GSMEMF);
    cudaFuncSetAttribute(gemm_f16_stream, cudaFuncAttributeMaxDynamicSharedMemorySize, GSMEMS);

    // 1) LN1 (bf16 split + fp16) fused with all weight prep
    stage1_kernel<<<LN_BLOCKS + PREP_BLOCKS, 128>>>(x, ln1_g, ln1_b, ln1, h1h,
                                                    Wq, Wk, Wv, Wp, W1, W2);
    // 2) fat QKV: QK (3-pass bf16) + V (1-pass fp16) in one launch
    gemm_qkv<<<dim3(9, N_TOK / 128), 256, GSMEM3>>>(ln1, wqk, h1h, wvh, qkv);
    // 3) attention -> fp16
    attn_kernel<<<dim3(2048, NHEAD), 128>>>(qkv, attnh);
    // 4) proj + bias + residual(x) -> fp32 x2
    gemm_f16<1><<<dim3(3, 64), 256, GSMEMF>>>(attnh, EMB, wph, EMB, bp, x, x2, EMB);
    // 5) LN2 -> fp16
    ln2_kernel<<<N_TOK / 4, 128>>>(x2, ln2_g, ln2_b, h2h);
    // 6) MLP up + relu -> fp16 hidden
    gemm_f16<2><<<dim3(12, 64), 256, GSMEMF>>>(h2h, EMB, w1h, EMB, b1, nullptr, hidh, FF);
    // 7) MLP down (K=1536) + bias + residual(x2) -> out
    gemm_f16_stream<<<dim3(3, N_TOK / 128), 256, GSMEMS>>>(hidh, w2h, b2, x2, out, FF, EMB);
}

// round 9
// speedup vs baseline: 2.2081x; 1.0814x over previous
#include <cuda_runtime.h>
#include <cuda_bf16.h>
#include <cuda_fp16.h>
#include <cstdint>

// ---------------- problem constants ----------------
constexpr int N_TOK  = 2048 * 64;   // 131072 tokens
constexpr int EMB    = 384;
constexpr int NHEAD  = 8;
constexpr int HSZ    = 48;
constexpr int SEQ    = 64;
constexpr int FF     = 1536;
constexpr float ATT_SCALE = 2.449489742783178f;

// ---------------- scratch (static device memory) ----------------
__device__ __align__(128) __nv_bfloat16 g_ln1 [(size_t)N_TOK * 2 * EMB];    // [hi|lo] for QK
__device__ __align__(128) __half        g_h1h [(size_t)N_TOK * EMB];        // fp16 LN1 (for V)
__device__ __align__(128) float         g_qkv [(size_t)N_TOK * 3 * EMB];    // fp32 q|k|v
__device__ __align__(128) __half        g_attnh[(size_t)N_TOK * EMB];       // fp16
__device__ __align__(128) float         g_x2  [(size_t)N_TOK * EMB];        // fp32 residual
__device__ __align__(128) __half        g_h2h [(size_t)N_TOK * EMB];        // fp16
__device__ __align__(128) __half        g_hidh[(size_t)N_TOK * FF];         // fp16
__device__ __align__(128) __nv_bfloat16 g_wqk [(size_t)(2*EMB) * 2 * EMB];  // [768][hi|lo 768]
__device__ __align__(128) __half        g_wvh [(size_t)EMB * EMB];          // [N][K] fp16
__device__ __align__(128) __half        g_wph [(size_t)EMB * EMB];
__device__ __align__(128) __half        g_w1h [(size_t)FF  * EMB];
__device__ __align__(128) __half        g_w2h [(size_t)EMB * FF];

// ---------------- PTX helpers ----------------
typedef unsigned long long u64;
__device__ __forceinline__ uint32_t smem_u32(const void* p) {
    uint32_t a;
    asm("{ .reg .u64 t; cvta.to.shared.u64 t, %1; cvt.u32.u64 %0, t; }" : "=r"(a) : "l"(p));
    return a;
}
#define CPASYNC16(dst, src) asm volatile("cp.async.cg.shared.global [%0], [%1], 16;" :: "r"(dst), "l"(src) : "memory")
#define CP_COMMIT()         asm volatile("cp.async.commit_group;" ::: "memory")
#define CP_WAIT1()          asm volatile("cp.async.wait_group 1;" ::: "memory")

#define LDSM4(r, addr) \
    asm volatile("ldmatrix.sync.aligned.m8n8.x4.shared.b16 {%0,%1,%2,%3}, [%4];" \
        : "=r"((r)[0]), "=r"((r)[1]), "=r"((r)[2]), "=r"((r)[3]) : "r"(addr))

#define MMA_BF16(d, a, b0, b1) \
    asm volatile("mma.sync.aligned.m16n8k16.row.col.f32.bf16.bf16.f32 " \
        "{%0,%1,%2,%3}, {%4,%5,%6,%7}, {%8,%9}, {%0,%1,%2,%3};" \
        : "+f"((d)[0]), "+f"((d)[1]), "+f"((d)[2]), "+f"((d)[3]) \
        : "r"((a)[0]), "r"((a)[1]), "r"((a)[2]), "r"((a)[3]), "r"(b0), "r"(b1))

#define MMA_FP16(d, a, b0, b1) \
    asm volatile("mma.sync.aligned.m16n8k16.row.col.f32.f16.f16.f32 " \
        "{%0,%1,%2,%3}, {%4,%5,%6,%7}, {%8,%9}, {%0,%1,%2,%3};" \
        : "+f"((d)[0]), "+f"((d)[1]), "+f"((d)[2]), "+f"((d)[3]) \
        : "r"((a)[0]), "r"((a)[1]), "r"((a)[2]), "r"((a)[3]), "r"(b0), "r"(b1))

__device__ __forceinline__ u64 pk2(float lo, float hi) {
    u64 r; asm("mov.b64 %0, {%1, %2};" : "=l"(r) : "f"(lo), "f"(hi)); return r;
}
__device__ __forceinline__ float2 upk2(u64 p) {
    float2 r; asm("mov.b64 {%0, %1}, %2;" : "=f"(r.x), "=f"(r.y) : "l"(p)); return r;
}
#define FMA2(d, a, b) asm("fma.rn.f32x2 %0, %1, %2, %0;" : "+l"(d) : "l"(a), "l"(b))
#define MUL2(d, a, b) asm("mul.rn.f32x2 %0, %1, %2;" : "=l"(d) : "l"(a), "l"(b))

__device__ __forceinline__ __nv_bfloat16 bf_hi(float v) { return __float2bfloat16(v); }
__device__ __forceinline__ __nv_bfloat16 bf_lo(float v, __nv_bfloat16 hi) {
    return __float2bfloat16(v - __bfloat162float(hi));
}

// ---------------- stage 1: LN1 (+split outputs) fused with ALL weight prep ----------------
constexpr int LN_BLOCKS   = N_TOK / 4;               // 32768
constexpr int PREP_TOTAL  = 147456 + 147456 + 589824 + 589824;  // 1474560
constexpr int PREP_BLOCKS = PREP_TOTAL / 512;        // 2880

__global__ void __launch_bounds__(128)
stage1_kernel(const float* __restrict__ in, const float* __restrict__ g,
              const float* __restrict__ b, __nv_bfloat16* __restrict__ bfout,
              __half* __restrict__ hout,
              const float* __restrict__ Wq, const float* __restrict__ Wk,
              const float* __restrict__ Wv, const float* __restrict__ Wp,
              const float* __restrict__ W1, const float* __restrict__ W2) {
    if (blockIdx.x < LN_BLOCKS) {
        const int row = blockIdx.x * 4 + (threadIdx.x >> 5);
        const int lane = threadIdx.x & 31;
        const float* rp = in + (size_t)row * EMB + lane * 12;
        float4 v0 = *(const float4*)(rp), v1 = *(const float4*)(rp + 4), v2 = *(const float4*)(rp + 8);
        float vv[12] = {v0.x, v0.y, v0.z, v0.w, v1.x, v1.y, v1.z, v1.w, v2.x, v2.y, v2.z, v2.w};
        float s = 0.0f, ss = 0.0f;
        #pragma unroll
        for (int i = 0; i < 12; i++) { s += vv[i]; ss += vv[i] * vv[i]; }
        #pragma unroll
        for (int off = 16; off > 0; off >>= 1) {
            s  += __shfl_xor_sync(0xffffffffu, s, off);
            ss += __shfl_xor_sync(0xffffffffu, ss, off);
        }
        float mu = s * (1.0f / EMB);
        float var = ss * (1.0f / EMB) - mu * mu;
        float rs = rsqrtf(var + 1e-5f);
        const float* gp = g + lane * 12;
        const float* bp = b + lane * 12;
        float o[12];
        #pragma unroll
        for (int i = 0; i < 12; i++) o[i] = (vv[i] - mu) * rs * gp[i] + bp[i];
        __half hh[12];
        #pragma unroll
        for (int i = 0; i < 12; i++) hh[i] = __float2half(o[i]);
        __half* hrow = hout + (size_t)row * EMB + lane * 12;
        *(uint2*)(hrow)     = *(uint2*)(hh);
        *(uint2*)(hrow + 4) = *(uint2*)(hh + 4);
        *(uint2*)(hrow + 8) = *(uint2*)(hh + 8);
        __nv_bfloat16 hi[12], lo[12];
        #pragma unroll
        for (int i = 0; i < 12; i++) { hi[i] = bf_hi(o[i]); lo[i] = bf_lo(o[i], hi[i]); }
        __nv_bfloat16* orow = bfout + (size_t)row * 2 * EMB + lane * 12;
        *(uint2*)(orow)     = *(uint2*)(hi);
        *(uint2*)(orow + 4) = *(uint2*)(hi + 4);
        *(uint2*)(orow + 8) = *(uint2*)(hi + 8);
        __nv_bfloat16* lrow = orow + EMB;
        *(uint2*)(lrow)     = *(uint2*)(lo);
        *(uint2*)(lrow + 4) = *(uint2*)(lo + 4);
        *(uint2*)(lrow + 8) = *(uint2*)(lo + 8);
    } else {
        int base = (blockIdx.x - LN_BLOCKS) * 512 + threadIdx.x * 4;
        #pragma unroll
        for (int e = 0; e < 4; e++) {
            int i = base + e;
            if (i < 147456) {
                int h = i / (EMB * HSZ), r = i % (EMB * HSZ), c = r / HSZ, d = r % HSZ;
                int n = h * HSZ + d;
                float q = Wq[i], k = Wk[i];
                __nv_bfloat16 qh = bf_hi(q), kh = bf_hi(k);
                size_t rq = (size_t)n * 2 * EMB, rk = (size_t)(EMB + n) * 2 * EMB;
                g_wqk[rq + c] = qh;  g_wqk[rq + EMB + c] = bf_lo(q, qh);
                g_wqk[rk + c] = kh;  g_wqk[rk + EMB + c] = bf_lo(k, kh);
                g_wvh[(size_t)n * EMB + c] = __float2half(Wv[i]);
            } else if (i < 294912) {
                int j = i - 147456;
                int k = j / EMB, n = j % EMB;
                g_wph[(size_t)n * EMB + k] = __float2half(Wp[j]);
            } else if (i < 884736) {
                int j = i - 294912;
                int k = j / FF, n = j % FF;
                g_w1h[(size_t)n * EMB + k] = __float2half(W1[j]);
            } else {
                int j = i - 884736;
                int k = j / EMB, n = j % EMB;
                g_w2h[(size_t)n * FF + k] = __float2half(W2[j]);
            }
        }
    }
}

// ---------------- LN2 (fp16 out only) ----------------
__global__ void __launch_bounds__(128)
ln2_kernel(const float* __restrict__ in, const float* __restrict__ g,
           const float* __restrict__ b, __half* __restrict__ hout) {
    const int row = blockIdx.x * 4 + (threadIdx.x >> 5);
    const int lane = threadIdx.x & 31;
    const float* rp = in + (size_t)row * EMB + lane * 12;
    float4 v0 = *(const float4*)(rp), v1 = *(const float4*)(rp + 4), v2 = *(const float4*)(rp + 8);
    float vv[12] = {v0.x, v0.y, v0.z, v0.w, v1.x, v1.y, v1.z, v1.w, v2.x, v2.y, v2.z, v2.w};
    float s = 0.0f, ss = 0.0f;
    #pragma unroll
    for (int i = 0; i < 12; i++) { s += vv[i]; ss += vv[i] * vv[i]; }
    #pragma unroll
    for (int off = 16; off > 0; off >>= 1) {
        s  += __shfl_xor_sync(0xffffffffu, s, off);
        ss += __shfl_xor_sync(0xffffffffu, ss, off);
    }
    float mu = s * (1.0f / EMB);
    float var = ss * (1.0f / EMB) - mu * mu;
    float rs = rsqrtf(var + 1e-5f);
    const float* gp = g + lane * 12;
    const float* bp = b + lane * 12;
    __half hh[12];
    #pragma unroll
    for (int i = 0; i < 12; i++) hh[i] = __float2half((vv[i] - mu) * rs * gp[i] + bp[i]);
    __half* hrow = hout + (size_t)row * EMB + lane * 12;
    *(uint2*)(hrow)     = *(uint2*)(hh);
    *(uint2*)(hrow + 4) = *(uint2*)(hh + 4);
    *(uint2*)(hrow + 8) = *(uint2*)(hh + 8);
}

// ---------------- shared tiling constants ----------------
constexpr int PIECE  = 128 * 144;     // 18432 bytes: 128 rows x 64 halves, 144B padded
constexpr int STAGE3 = 4 * PIECE;     // QK stage: Ah|Al|Bh|Bl
constexpr int GSMEM3 = 3 * STAGE3;    // 221184
constexpr int FSTAGE = 2 * PIECE;     // fp16 stage: A|B
constexpr int GSMEMS = 3 * FSTAGE;    // 110592

// ================= unified 512-thread streaming fp16 GEMM =================
// BM=BN=128, 16 warps (4x4), warp tile 32x32, 3-stage ring.
template<int MODE>  // 0: fp32=acc  1: fp32=acc+bias+res  2: fp16=relu(acc+bias)
__global__ void __launch_bounds__(512, 1)
gemm16(const __half* __restrict__ A, const __half* __restrict__ B,
       const float* __restrict__ bias, const float* __restrict__ res,
       void* __restrict__ out, int Kw, int Ntot, int col0) {
    extern __shared__ char smem[];
    const uint32_t sbase = smem_u32(smem);
    const int tid = threadIdx.x, lane = tid & 31, wid = tid >> 5;
    const int wm = wid >> 2, wn = wid & 3;
    const int m0 = blockIdx.y * 128, n0 = blockIdx.x * 128;
    const int nstages = Kw >> 6;

    // loader: 512 threads, 2 chunks per piece each
    const int lrow = tid >> 2, lq = tid & 3;
    const __half* agp = A + (size_t)(m0 + lrow) * Kw + lq * 16;
    const __half* bgp = B + (size_t)(n0 + lrow) * Kw + lq * 16;
    const uint32_t ldst = (uint32_t)(lrow * 144 + lq * 32);

#define LOAD_F(bufi, k0v) do { \
        const uint32_t sb = sbase + (bufi) * FSTAGE; \
        CPASYNC16(sb + ldst,      agp + (k0v));          CPASYNC16(sb + ldst + 16, agp + (k0v) + 8); \
        CPASYNC16(sb + PIECE + ldst, bgp + (k0v));       CPASYNC16(sb + PIECE + ldst + 16, bgp + (k0v) + 8); \
    } while (0)

    float d[2][4][4];
    #pragma unroll
    for (int i = 0; i < 2; i++)
        #pragma unroll
        for (int j = 0; j < 4; j++)
            #pragma unroll
            for (int q = 0; q < 4; q++) d[i][j][q] = 0.0f;

    const uint32_t a_off = (uint32_t)((wm * 32 + (lane & 15)) * 144 + (lane >> 4) * 16);
    const int nl = (lane & 7) + ((lane >> 4) << 3);
    const int kc = (lane >> 3) & 1;
    const uint32_t b_off = (uint32_t)((wn * 32 + nl) * 144 + kc * 16);

    LOAD_F(0, 0);  CP_COMMIT();
    LOAD_F(1, 64); CP_COMMIT();

    for (int it = 0; it < nstages; it++) {
        CP_WAIT1();
        __syncthreads();
        if (it + 2 < nstages) LOAD_F((it + 2) % 3, (it + 2) * 64);
        CP_COMMIT();

        const uint32_t sA = sbase + (it % 3) * FSTAGE;
        const uint32_t sB = sA + PIECE;
        #pragma unroll
        for (int kk = 0; kk < 4; kk++) {
            uint32_t a[2][4], b[2][4];
            #pragma unroll
            for (int mi = 0; mi < 2; mi++)
                LDSM4(a[mi], sA + a_off + mi * (16 * 144) + kk * 32);
            #pragma unroll
            for (int np = 0; np < 2; np++)
                LDSM4(b[np], sB + b_off + np * (16 * 144) + kk * 32);
            #pragma unroll
            for (int mi = 0; mi < 2; mi++)
                #pragma unroll
                for (int np = 0; np < 2; np++)
                    #pragma unroll
                    for (int sub = 0; sub < 2; sub++)
                        MMA_FP16(d[mi][np * 2 + sub], a[mi], b[np][sub*2], b[np][sub*2+1]);
        }
    }
#undef LOAD_F

    #pragma unroll
    for (int mi = 0; mi < 2; mi++) {
        int row0 = m0 + wm * 32 + mi * 16 + (lane >> 2);
        #pragma unroll
        for (int ni = 0; ni < 4; ni++) {
            int col = col0 + n0 + wn * 32 + ni * 8 + (lane & 3) * 2;
            if (MODE == 0) {
                float* o = (float*)out;
                *(float2*)(o + (size_t)row0 * Ntot + col)       = make_float2(d[mi][ni][0], d[mi][ni][1]);
                *(float2*)(o + (size_t)(row0 + 8) * Ntot + col) = make_float2(d[mi][ni][2], d[mi][ni][3]);
            } else if (MODE == 1) {
                float b0 = bias[col], b1 = bias[col + 1];
                float* o = (float*)out;
                float2 r0 = *(const float2*)(res + (size_t)row0 * Ntot + col);
                float2 r1 = *(const float2*)(res + (size_t)(row0 + 8) * Ntot + col);
                *(float2*)(o + (size_t)row0 * Ntot + col) =
                    make_float2(d[mi][ni][0] + b0 + r0.x, d[mi][ni][1] + b1 + r0.y);
                *(float2*)(o + (size_t)(row0 + 8) * Ntot + col) =
                    make_float2(d[mi][ni][2] + b0 + r1.x, d[mi][ni][3] + b1 + r1.y);
            } else {
                float b0 = bias[col], b1 = bias[col + 1];
                __half* ob = (__half*)out;
                *(__half2*)(ob + (size_t)row0 * Ntot + col) =
                    __floats2half2_rn(fmaxf(d[mi][ni][0] + b0, 0.0f), fmaxf(d[mi][ni][1] + b1, 0.0f));
                *(__half2*)(ob + (size_t)(row0 + 8) * Ntot + col) =
                    __floats2half2_rn(fmaxf(d[mi][ni][2] + b0, 0.0f), fmaxf(d[mi][ni][3] + b1, 0.0f));
            }
        }
    }
}

// ================= fat QKV kernel, 512 threads =================
// blockIdx.x < 6: QK 3-pass bf16;  >= 6: V 1-pass fp16.
__global__ void __launch_bounds__(512, 1)
gemm_qkv(const __nv_bfloat16* __restrict__ Aqk, const __nv_bfloat16* __restrict__ Bqk,
         const __half* __restrict__ Av, const __half* __restrict__ Bv,
         float* __restrict__ out) {
    extern __shared__ char smem[];
    const uint32_t sbase = smem_u32(smem);
    const int tid = threadIdx.x, lane = tid & 31, wid = tid >> 5;
    const int wm = wid >> 2, wn = wid & 3;
    const int m0 = blockIdx.y * 128;
    const int lrow = tid >> 2, lq = tid & 3;
    const uint32_t ldst = (uint32_t)(lrow * 144 + lq * 32);
    const uint32_t a_off = (uint32_t)((wm * 32 + (lane & 15)) * 144 + (lane >> 4) * 16);
    const int nl = (lane & 7) + ((lane >> 4) << 3);
    const int kc = (lane >> 3) & 1;
    const uint32_t b_off = (uint32_t)((wn * 32 + nl) * 144 + kc * 16);

    float d[2][4][4];
    #pragma unroll
    for (int i = 0; i < 2; i++)
        #pragma unroll
        for (int j = 0; j < 4; j++)
            #pragma unroll
            for (int q = 0; q < 4; q++) d[i][j][q] = 0.0f;

    if (blockIdx.x < 6) {
        const int n0 = blockIdx.x * 128;
        const __nv_bfloat16* agp = Aqk + (size_t)(m0 + lrow) * (2 * EMB) + lq * 16;
        const __nv_bfloat16* bgp = Bqk + (size_t)(n0 + lrow) * (2 * EMB) + lq * 16;

#define LOAD_QK(bufi, k0v) do { \
        const uint32_t sb = sbase + (bufi) * STAGE3; \
        CPASYNC16(sb + ldst,      agp + (k0v));              CPASYNC16(sb + ldst + 16, agp + (k0v) + 8); \
        CPASYNC16(sb + PIECE + ldst, agp + EMB + (k0v));     CPASYNC16(sb + PIECE + ldst + 16, agp + EMB + (k0v) + 8); \
        CPASYNC16(sb + 2*PIECE + ldst, bgp + (k0v));         CPASYNC16(sb + 2*PIECE + ldst + 16, bgp + (k0v) + 8); \
        CPASYNC16(sb + 3*PIECE + ldst, bgp + EMB + (k0v));   CPASYNC16(sb + 3*PIECE + ldst + 16, bgp + EMB + (k0v) + 8); \
    } while (0)

        LOAD_QK(0, 0);  CP_COMMIT();
        LOAD_QK(1, 64); CP_COMMIT();

        #pragma unroll 1
        for (int it = 0; it < 6; it++) {
            CP_WAIT1();
            __syncthreads();
            if (it + 2 < 6) LOAD_QK((it + 2) % 3, (it + 2) * 64);
            CP_COMMIT();

            const uint32_t sA = sbase + (it % 3) * STAGE3;
            const uint32_t sB = sA + 2 * PIECE;
            #pragma unroll
            for (int kk = 0; kk < 4; kk++) {
                uint32_t a[2][2][4], b[2][2][4];
                #pragma unroll
                for (int sp = 0; sp < 2; sp++)
                    #pragma unroll
                    for (int mi = 0; mi < 2; mi++)
                        LDSM4(a[sp][mi], sA + sp * PIECE + a_off + mi * (16 * 144) + kk * 32);
                #pragma unroll
                for (int sp = 0; sp < 2; sp++)
                    #pragma unroll
                    for (int np = 0; np < 2; np++)
                        LDSM4(b[sp][np], sB + sp * PIECE + b_off + np * (16 * 144) + kk * 32);
                #pragma unroll
                for (int mi = 0; mi < 2; mi++)
                    #pragma unroll
                    for (int np = 0; np < 2; np++)
                        #pragma unroll
                        for (int sub = 0; sub < 2; sub++)
                            MMA_BF16(d[mi][np * 2 + sub], a[0][mi], b[0][np][sub*2], b[0][np][sub*2+1]);
                #pragma unroll
                for (int mi = 0; mi < 2; mi++)
                    #pragma unroll
                    for (int np = 0; np < 2; np++)
                        #pragma unroll
                        for (int sub = 0; sub < 2; sub++)
                            MMA_BF16(d[mi][np * 2 + sub], a[0][mi], b[1][np][sub*2], b[1][np][sub*2+1]);
                #pragma unroll
                for (int mi = 0; mi < 2; mi++)
                    #pragma unroll
                    for (int np = 0; np < 2; np++)
                        #pragma unroll
                        for (int sub = 0; sub < 2; sub++)
                            MMA_BF16(d[mi][np * 2 + sub], a[1][mi], b[0][np][sub*2], b[0][np][sub*2+1]);
            }
        }
#undef LOAD_QK

        #pragma unroll
        for (int mi = 0; mi < 2; mi++) {
            int row0 = m0 + wm * 32 + mi * 16 + (lane >> 2);
            #pragma unroll
            for (int ni = 0; ni < 4; ni++) {
                int col = n0 + wn * 32 + ni * 8 + (lane & 3) * 2;
                *(float2*)(out + (size_t)row0 * (3 * EMB) + col)       = make_float2(d[mi][ni][0], d[mi][ni][1]);
                *(float2*)(out + (size_t)(row0 + 8) * (3 * EMB) + col) = make_float2(d[mi][ni][2], d[mi][ni][3]);
            }
        }
    } else {
        const int n0 = (blockIdx.x - 6) * 128;
        const __half* agp = Av + (size_t)(m0 + lrow) * EMB + lq * 16;
        const __half* bgp = Bv + (size_t)(n0 + lrow) * EMB + lq * 16;

#define LOAD_V(bufi, k0v) do { \
        const uint32_t sb = sbase + (bufi) * FSTAGE; \
        CPASYNC16(sb + ldst,      agp + (k0v));          CPASYNC16(sb + ldst + 16, agp + (k0v) + 8); \
        CPASYNC16(sb + PIECE + ldst, bgp + (k0v));       CPASYNC16(sb + PIECE + ldst + 16, bgp + (k0v) + 8); \
    } while (0)

        LOAD_V(0, 0);  CP_COMMIT();
        LOAD_V(1, 64); CP_COMMIT();

        #pragma unroll 1
        for (int it = 0; it < 6; it++) {
            CP_WAIT1();
            __syncthreads();
            if (it + 2 < 6) LOAD_V((it + 2) % 3, (it + 2) * 64);
            CP_COMMIT();

            const uint32_t sA = sbase + (it % 3) * FSTAGE;
            const uint32_t sB = sA + PIECE;
            #pragma unroll
            for (int kk = 0; kk < 4; kk++) {
                uint32_t a[2][4], b[2][4];
                #pragma unroll
                for (int mi = 0; mi < 2; mi++)
                    LDSM4(a[mi], sA + a_off + mi * (16 * 144) + kk * 32);
                #pragma unroll
                for (int np = 0; np < 2; np++)
                    LDSM4(b[np], sB + b_off + np * (16 * 144) + kk * 32);
                #pragma unroll
                for (int mi = 0; mi < 2; mi++)
                    #pragma unroll
                    for (int np = 0; np < 2; np++)
                        #pragma unroll
                        for (int sub = 0; sub < 2; sub++)
                            MMA_FP16(d[mi][np * 2 + sub], a[mi], b[np][sub*2], b[np][sub*2+1]);
            }
        }
#undef LOAD_V

        #pragma unroll
        for (int mi = 0; mi < 2; mi++) {
            int row0 = m0 + wm * 32 + mi * 16 + (lane >> 2);
            #pragma unroll
            for (int ni = 0; ni < 4; ni++) {
                int col = 2 * EMB + n0 + wn * 32 + ni * 8 + (lane & 3) * 2;
                *(float2*)(out + (size_t)row0 * (3 * EMB) + col)       = make_float2(d[mi][ni][0], d[mi][ni][1]);
                *(float2*)(out + (size_t)(row0 + 8) * (3 * EMB) + col) = make_float2(d[mi][ni][2], d[mi][ni][3]);
            }
        }
    }
}

// ---------------- attention (fp32 in, fp16 out) with f32x2 packed math ----------------
__global__ void __launch_bounds__(128)
attn_kernel(const float* __restrict__ qkv, __half* __restrict__ out) {
    const int b = blockIdx.x, h = blockIdx.y;
    const int tid = threadIdx.x;
    const int r = tid >> 1, half = tid & 1;
    __shared__ float ks[SEQ][HSZ];
    __shared__ float vs[SEQ][HSZ];

    for (int i = tid; i < SEQ * (HSZ / 4); i += 128) {
        int s = i / (HSZ / 4), c = i % (HSZ / 4);
        const float* src = qkv + (size_t)(b * SEQ + s) * (3 * EMB) + h * HSZ;
        *(float4*)&ks[s][c * 4] = *(const float4*)(src + EMB + c * 4);
        *(float4*)&vs[s][c * 4] = *(const float4*)(src + 2 * EMB + c * 4);
    }
    u64 q2[12];
    {
        const float* qsrc = qkv + (size_t)(b * SEQ + r) * (3 * EMB) + h * HSZ + half * 24;
        #pragma unroll
        for (int i = 0; i < 6; i++) {
            float4 v = *(const float4*)(qsrc + 4 * i);
            q2[2 * i]     = pk2(v.x, v.y);
            q2[2 * i + 1] = pk2(v.z, v.w);
        }
    }
    __syncthreads();

    const uint32_t pmask = 3u << ((tid & 31) & ~1);
    float m = -1e30f, l = 0.0f;
    u64 o2[12];
    #pragma unroll
    for (int i = 0; i < 12; i++) o2[i] = 0ull;

    for (int s0 = 0; s0 <= r; s0 += 16) {
        float sc[16];
        float bm = -1e30f;
        #pragma unroll
        for (int j = 0; j < 16; j++) {
            int s = s0 + j;
            float pd = 0.0f;
            if (s <= r) {
                const u64* kp2 = (const u64*)&ks[s][half * 24];
                u64 acc = 0ull;
                #pragma unroll
                for (int i = 0; i < 12; i++) FMA2(acc, q2[i], kp2[i]);
                float2 ac = upk2(acc);
                pd = ac.x + ac.y;
            }
            pd += __shfl_xor_sync(pmask, pd, 1);
            sc[j] = (s <= r) ? pd * ATT_SCALE : -1e30f;
            bm = fmaxf(bm, sc[j]);
        }
        float nm = fmaxf(m, bm);
        float alpha = __expf(m - nm);
        l *= alpha;
        u64 a2 = pk2(alpha, alpha);
        #pragma unroll
        for (int i = 0; i < 12; i++) { u64 t; MUL2(t, o2[i], a2); o2[i] = t; }
        #pragma unroll
        for (int j = 0; j < 16; j++) {
            float p = __expf(sc[j] - nm);
            l += p;
            int sv = s0 + j; sv = sv < SEQ ? sv : SEQ - 1;
            const u64* vp2 = (const u64*)&vs[sv][half * 24];
            u64 p2v = pk2(p, p);
            #pragma unroll
            for (int i = 0; i < 12; i++) FMA2(o2[i], p2v, vp2[i]);
        }
        m = nm;
    }
    float inv = 1.0f / l;
    __half* op = out + (size_t)(b * SEQ + r) * EMB + h * HSZ + half * 24;
    #pragma unroll
    for (int i = 0; i < 12; i++) {
        float2 f = upk2(o2[i]);
        *(__half2*)(op + 2 * i) = __floats2half2_rn(f.x * inv, f.y * inv);
    }
}

// ---------------- launch ----------------
extern "C" void kernel_launch(void* const* d_in, const int* in_sizes, int n_in,
                              void* d_out, int out_size) {
    const float* x     = (const float*)d_in[0];
    const float* ln1_g = (const float*)d_in[1];
    const float* ln1_b = (const float*)d_in[2];
    const float* ln2_g = (const float*)d_in[3];
    const float* ln2_b = (const float*)d_in[4];
    const float* Wq    = (const float*)d_in[5];
    const float* Wk    = (const float*)d_in[6];
    const float* Wv    = (const float*)d_in[7];
    const float* Wp    = (const float*)d_in[8];
    const float* bp    = (const float*)d_in[9];
    const float* W1    = (const float*)d_in[10];
    const float* b1    = (const float*)d_in[11];
    const float* W2    = (const float*)d_in[12];
    const float* b2    = (const float*)d_in[13];
    float* out = (float*)d_out;

    __nv_bfloat16 *ln1, *wqk;
    __half *h1h, *attnh, *h2h, *hidh, *wvh, *wph, *w1h, *w2h;
    float *qkv, *x2;
    cudaGetSymbolAddress((void**)&ln1,   g_ln1);
    cudaGetSymbolAddress((void**)&h1h,   g_h1h);
    cudaGetSymbolAddress((void**)&qkv,   g_qkv);
    cudaGetSymbolAddress((void**)&attnh, g_attnh);
    cudaGetSymbolAddress((void**)&x2,    g_x2);
    cudaGetSymbolAddress((void**)&h2h,   g_h2h);
    cudaGetSymbolAddress((void**)&hidh,  g_hidh);
    cudaGetSymbolAddress((void**)&wqk,   g_wqk);
    cudaGetSymbolAddress((void**)&wvh,   g_wvh);
    cudaGetSymbolAddress((void**)&wph,   g_wph);
    cudaGetSymbolAddress((void**)&w1h,   g_w1h);
    cudaGetSymbolAddress((void**)&w2h,   g_w2h);

    cudaFuncSetAttribute(gemm_qkv,   cudaFuncAttributeMaxDynamicSharedMemorySize, GSMEM3);
    cudaFuncSetAttribute(gemm16<1>,  cudaFuncAttributeMaxDynamicSharedMemorySize, GSMEMS);
    cudaFuncSetAttribute(gemm16<2>,  cudaFuncAttributeMaxDynamicSharedMemorySize, GSMEMS);

    // 1) LN1 (bf16 split + fp16) fused with all weight prep
    stage1_kernel<<<LN_BLOCKS + PREP_BLOCKS, 128>>>(x, ln1_g, ln1_b, ln1, h1h,
                                                    Wq, Wk, Wv, Wp, W1, W2);
    // 2) fat QKV: QK (3-pass bf16) + V (1-pass fp16)
    gemm_qkv<<<dim3(9, N_TOK / 128), 512, GSMEM3>>>(ln1, wqk, h1h, wvh, qkv);
    // 3) attention -> fp16
    attn_kernel<<<dim3(2048, NHEAD), 128>>>(qkv, attnh);
    // 4) proj + bias + residual(x) -> fp32 x2
    gemm16<1><<<dim3(3, N_TOK / 128), 512, GSMEMS>>>(attnh, wph, bp, x, x2, EMB, EMB, 0);
    // 5) LN2 -> fp16
    ln2_kernel<<<N_TOK / 4, 128>>>(x2, ln2_g, ln2_b, h2h);
    // 6) MLP up + relu -> fp16 hidden
    gemm16<2><<<dim3(12, N_TOK / 128), 512, GSMEMS>>>(h2h, w1h, b1, nullptr, hidh, EMB, FF, 0);
    // 7) MLP down (K=1536) + bias + residual(x2) -> out
    gemm16<1><<<dim3(3, N_TOK / 128), 512, GSMEMS>>>(hidh, w2h, b2, x2, out, FF, EMB, 0);
}